// round 12
// baseline (speedup 1.0000x reference)
#include <cuda_runtime.h>
#include <math.h>
#include <stdint.h>

#define D_ 512
#define B_ 16
#define LQ_ 1024
#define LK_ 1024
#define NROW_ (B_*LQ_)

// ---------------- scratch globals (tf32-rounded, k-permuted planes) --------
__device__ __align__(16) float g_qp[NROW_*D_];
__device__ __align__(16) float g_kp[NROW_*D_];
__device__ __align__(16) float g_vpin[NROW_*D_];
__device__ __align__(16) float g_wvp[D_*D_];
__device__ __align__(16) float g_w1p[D_*D_];
__device__ __align__(16) float g_w2p[(D_/2)*D_];
__device__ __align__(16) float g_vpt[B_*D_*LK_];
__device__ __align__(16) float g_scores[(long long)B_*LQ_*LK_];
__device__ __align__(16) float g_wt[(long long)B_*LQ_*LK_];
__device__ __align__(16) float g_attn[NROW_*D_];
__device__ __align__(16) float g_h1[NROW_*D_];
__device__ float g_fbw[NROW_];
__device__ float g_def[B_*D_], g_dh1[B_*D_], g_dh2[B_*(D_/2)];
__device__ unsigned g_umax, g_umin;
__device__ int g_maskmode;

// ---------------- helpers ---------------------------------------------------
__device__ __forceinline__ unsigned fmap(float f){
    unsigned u = __float_as_uint(f);
    return (u & 0x80000000u) ? ~u : (u | 0x80000000u);
}
__device__ __forceinline__ float funmap(unsigned m){
    return (m & 0x80000000u) ? __uint_as_float(m ^ 0x80000000u) : __uint_as_float(~m);
}
__device__ __forceinline__ float tf32r(float x){
    unsigned r; asm("cvt.rna.tf32.f32 %0, %1;" : "=r"(r) : "f"(x));
    return __uint_as_float(r);
}
__device__ __forceinline__ int kperm(int c){
    return (c & ~7) | ((c & 3) << 1) | ((c >> 2) & 1);
}
#define CPA16(sa, gp) asm volatile("cp.async.cg.shared.global [%0], [%1], 16;\n" :: "r"(sa), "l"(gp))
#define CPA_COMMIT() asm volatile("cp.async.commit_group;\n" ::: "memory")
#define CPA_WAIT1()  asm volatile("cp.async.wait_group 1;\n" ::: "memory")

#define MMA_TF32(acc, a0, a1, a2, a3, b0, b1) \
    asm volatile( \
        "mma.sync.aligned.m16n8k8.row.col.f32.tf32.tf32.f32 " \
        "{%0,%1,%2,%3}, {%4,%5,%6,%7}, {%8,%9}, {%0,%1,%2,%3};" \
        : "+f"((acc)[0]), "+f"((acc)[1]), "+f"((acc)[2]), "+f"((acc)[3]) \
        : "r"(a0), "r"(a1), "r"(a2), "r"(a3), "r"(b0), "r"(b1))

// ---------------- init + mask dtype detection ------------------------------
__global__ void k_init_detect(const unsigned char* __restrict__ mb){
    __shared__ int sGE2, sOff;
    int tid = threadIdx.x;
    if (tid == 0){ sGE2 = 0; sOff = 0; g_umax = 0u; g_umin = 0xFFFFFFFFu; }
    __syncthreads();
    int ge2 = 0, off = 0;
    for (int i = tid; i < B_*LK_; i += blockDim.x){
        unsigned char c = mb[i];
        if (c > 1) ge2 = 1;
        else if (c == 1 && (i & 3)) off = 1;
    }
    if (ge2) sGE2 = 1;
    if (off) sOff = 1;
    __syncthreads();
    if (tid == 0) g_maskmode = sGE2 ? 2 : (sOff ? 0 : 1);
}

// ---------------- converts: f32 -> tf32-rounded, k-permuted ----------------
__device__ __forceinline__ void cvt4(const float4* x, float* y, int i){
    float4 v = x[i];
    int base = i * 4;
    y[kperm(base  )] = tf32r(v.x);
    y[kperm(base+1)] = tf32r(v.y);
    y[kperm(base+2)] = tf32r(v.z);
    y[kperm(base+3)] = tf32r(v.w);
}
__global__ void k_cvt1(const float4* __restrict__ x, float* __restrict__ y, int n4){
    int i = blockIdx.x * blockDim.x + threadIdx.x;
    if (i < n4) cvt4(x, y, i);
}
__global__ void k_cvt3(const float4* __restrict__ x0, float* __restrict__ y0,
                       const float4* __restrict__ x1, float* __restrict__ y1,
                       const float4* __restrict__ x2, float* __restrict__ y2,
                       int n40, int n41, int n42){
    int i = blockIdx.x * blockDim.x + threadIdx.x;
    int z = blockIdx.y;
    if (z == 0){ if (i < n40) cvt4(x0, y0, i); }
    else if (z == 1){ if (i < n41) cvt4(x1, y1, i); }
    else { if (i < n42) cvt4(x2, y2, i); }
}

// =================== tf32 mma.sync NT GEMM engine (round-7 best) ===========
#define ASTR 40
#define AW (128*ASTR)
#define BW (256*ASTR)
#define STGW (AW+BW)
#define ENG_SMEM (3*STGW*4)

template<int EPI>
__global__ void __launch_bounds__(256, 1)
k6(const float* __restrict__ A, const float* __restrict__ Bm,
   const float* __restrict__ bias, float* __restrict__ C,
   int N, int K, long long sA, long long sB, long long sC, float scale,
   const float* __restrict__ fbw, const float* __restrict__ defv, int zofs)
{
    extern __shared__ float dsm[];
    __shared__ float red[512];

    const int bz = blockIdx.z + zofs;
    A  += (long long)bz * sA;
    Bm += (long long)bz * sB;
    C  += (long long)bz * sC;

    const int m0 = blockIdx.y * 128, n0 = blockIdx.x * 256;
    const int tid = threadIdx.x, lane = tid & 31, warp = tid >> 5;
    const int rbase = (warp & 1) * 64;
    const int cbase = (warp >> 1) * 64;
    const int grp = lane >> 2, qd = lane & 3;

    float* As = dsm;
    float* Bs = dsm + 3*AW;
    const unsigned asu = (unsigned)__cvta_generic_to_shared(As);
    const unsigned bsu = (unsigned)__cvta_generic_to_shared(Bs);

    const int niter = K >> 5;

    auto load_stage = [&](int g){
        const int buf = g % 3;
        const int k0 = g << 5;
        const unsigned ab = asu + buf * (AW*4);
        const unsigned bb = bsu + buf * (BW*4);
        #pragma unroll
        for (int i = 0; i < 4; i++){
            int id = tid + 256*i, row = id >> 3, ch = (id & 7) * 4;
            CPA16(ab + (unsigned)(row*ASTR + ch)*4,
                  A + (long long)(m0 + row)*K + k0 + ch);
        }
        #pragma unroll
        for (int i = 0; i < 8; i++){
            int id = tid + 256*i, row = id >> 3, ch = (id & 7) * 4;
            CPA16(bb + (unsigned)(row*ASTR + ch)*4,
                  Bm + (long long)(n0 + row)*K + k0 + ch);
        }
    };

    float acc[4][8][4];
    #pragma unroll
    for (int mt = 0; mt < 4; mt++)
        #pragma unroll
        for (int u = 0; u < 8; u++)
            #pragma unroll
            for (int r = 0; r < 4; r++) acc[mt][u][r] = 0.f;

    load_stage(0); CPA_COMMIT();
    load_stage(1); CPA_COMMIT();

    for (int it = 0; it < niter; ++it){
        CPA_WAIT1();
        __syncthreads();
        const float* As_s = As + (it % 3)*AW;
        const float* Bs_s = Bs + (it % 3)*BW;
        #pragma unroll
        for (int kk = 0; kk < 32; kk += 8){
            uint2 aLo[4], aHi[4], bF[8];
            #pragma unroll
            for (int mt = 0; mt < 4; mt++){
                const int m = rbase + mt*16 + grp;
                aLo[mt] = *(const uint2*)&As_s[m*ASTR + kk + 2*qd];
                aHi[mt] = *(const uint2*)&As_s[(m+8)*ASTR + kk + 2*qd];
            }
            #pragma unroll
            for (int u = 0; u < 8; u++){
                const int n = cbase + u*8 + grp;
                bF[u] = *(const uint2*)&Bs_s[n*ASTR + kk + 2*qd];
            }
            #pragma unroll
            for (int mt = 0; mt < 4; mt++)
                #pragma unroll
                for (int u = 0; u < 8; u++)
                    MMA_TF32(acc[mt][u], aLo[mt].x, aHi[mt].x, aLo[mt].y, aHi[mt].y,
                             bF[u].x, bF[u].y);
        }
        __syncthreads();
        if (it + 2 < niter) load_stage(it + 2);
        CPA_COMMIT();
    }

    if (EPI == 0){
        float lmax = -INFINITY, lmin = INFINITY;
        #pragma unroll
        for (int mt = 0; mt < 4; mt++){
            const int row = m0 + rbase + mt*16 + grp;
            #pragma unroll
            for (int u = 0; u < 8; u++){
                const int col = n0 + cbase + u*8 + qd*2;
                float v0 = acc[mt][u][0]*scale, v1 = acc[mt][u][1]*scale;
                float v2 = acc[mt][u][2]*scale, v3 = acc[mt][u][3]*scale;
                lmax = fmaxf(fmaxf(lmax, fmaxf(v0,v1)), fmaxf(v2,v3));
                lmin = fminf(fminf(lmin, fminf(v0,v1)), fminf(v2,v3));
                *(float2*)(C + (long long)row*N + col)     = make_float2(v0, v1);
                *(float2*)(C + (long long)(row+8)*N + col) = make_float2(v2, v3);
            }
        }
        red[tid] = lmax; red[256+tid] = lmin;
        __syncthreads();
        for (int st = 128; st > 0; st >>= 1){
            if (tid < st){
                red[tid]     = fmaxf(red[tid],     red[tid+st]);
                red[256+tid] = fminf(red[256+tid], red[256+tid+st]);
            }
            __syncthreads();
        }
        if (tid == 0){
            atomicMax(&g_umax, fmap(red[0]));
            atomicMin(&g_umin, fmap(red[256]));
        }
    } else if (EPI == 2 || EPI == 3){
        #pragma unroll
        for (int mt = 0; mt < 4; mt++){
            const int row = m0 + rbase + mt*16 + grp;
            float fw0 = 0.f, fw1 = 0.f;
            if (EPI == 2){ fw0 = fbw[bz*LQ_ + row]; fw1 = fbw[bz*LQ_ + row + 8]; }
            #pragma unroll
            for (int u = 0; u < 8; u++){
                const int col = n0 + cbase + u*8 + qd*2;
                float v0 = acc[mt][u][0], v1 = acc[mt][u][1];
                float v2 = acc[mt][u][2], v3 = acc[mt][u][3];
                const int p0 = n0 + cbase + u*8 + kperm(qd*2);
                const int p1 = n0 + cbase + u*8 + kperm(qd*2 + 1);
                if (EPI == 2){
                    float d0 = defv[bz*D_ + col], d1 = defv[bz*D_ + col + 1];
                    C[(long long)row*N + p0]     = tf32r(v0 + fw0*d0);
                    C[(long long)row*N + p1]     = tf32r(v1 + fw0*d1);
                    C[(long long)(row+8)*N + p0] = tf32r(v2 + fw1*d0);
                    C[(long long)(row+8)*N + p1] = tf32r(v3 + fw1*d1);
                } else {
                    float b0 = bias[col], b1 = bias[col+1];
                    C[(long long)row*N + p0]     = tf32r(fmaxf(v0 + b0, 0.f));
                    C[(long long)row*N + p1]     = tf32r(fmaxf(v1 + b1, 0.f));
                    C[(long long)(row+8)*N + p0] = tf32r(fmaxf(v2 + b0, 0.f));
                    C[(long long)(row+8)*N + p1] = tf32r(fmaxf(v3 + b1, 0.f));
                }
            }
        }
    } else if (EPI == 5){
        #pragma unroll
        for (int mt = 0; mt < 4; mt++){
            const int r0 = m0 + rbase + mt*16 + grp;
            const int r1 = r0 + 8;
            const int b0i = r0 >> 10, l0i = r0 & 1023;
            const int b1i = r1 >> 10, l1i = r1 & 1023;
            const long long o0 = (long long)b0i*D_*LK_ + kperm(l0i);
            const long long o1 = (long long)b1i*D_*LK_ + kperm(l1i);
            #pragma unroll
            for (int u = 0; u < 8; u++){
                const int col = n0 + cbase + u*8 + qd*2;
                const float bb0 = bias[col], bb1 = bias[col+1];
                C[o0 + (long long)col*LK_]     = tf32r(acc[mt][u][0] + bb0);
                C[o0 + (long long)(col+1)*LK_] = tf32r(acc[mt][u][1] + bb1);
                C[o1 + (long long)col*LK_]     = tf32r(acc[mt][u][2] + bb0);
                C[o1 + (long long)(col+1)*LK_] = tf32r(acc[mt][u][3] + bb1);
            }
        }
    } else if (EPI == 6){
        float part[8];
        #pragma unroll
        for (int i = 0; i < 8; i++) part[i] = 0.f;
        #pragma unroll
        for (int u = 0; u < 8; u++){
            const int col = cbase + u*8 + qd*2;
            const float w0 = fbw[col], w1 = fbw[col+1];
            const float b0 = bias[col], b1 = bias[col+1];
            #pragma unroll
            for (int mt = 0; mt < 4; mt++){
                part[mt*2]   += fmaxf(acc[mt][u][0]+b0, 0.f)*w0 + fmaxf(acc[mt][u][1]+b1, 0.f)*w1;
                part[mt*2+1] += fmaxf(acc[mt][u][2]+b0, 0.f)*w0 + fmaxf(acc[mt][u][3]+b1, 0.f)*w1;
            }
        }
        #pragma unroll
        for (int i = 0; i < 8; i++){
            part[i] += __shfl_xor_sync(0xffffffffu, part[i], 1);
            part[i] += __shfl_xor_sync(0xffffffffu, part[i], 2);
        }
        if (qd == 0){
            const int cg = warp >> 1;
            #pragma unroll
            for (int mt = 0; mt < 4; mt++){
                red[(rbase + mt*16 + grp)*4 + cg]     = part[mt*2];
                red[(rbase + mt*16 + grp + 8)*4 + cg] = part[mt*2+1];
            }
        }
        __syncthreads();
        if (tid < 128){
            float s = red[tid*4] + red[tid*4+1] + red[tid*4+2] + red[tid*4+3];
            C[m0 + tid] = tanhf(s + defv[0]);
        }
    }
}

// ---------------- tiny SIMT GEMM (M=16 paths, raw f32) ---------------------
__global__ void k_small(const float* __restrict__ A, const float* __restrict__ W,
                        const float* __restrict__ bias, float* __restrict__ C,
                        int M, int N, int K, int act)
{
    int g = blockIdx.x*8 + (threadIdx.x>>5), lane = threadIdx.x & 31;
    int m = g / N, n = g % N;
    if (m >= M) return;
    float s = 0.f;
    for (int k = lane; k < K; k += 32) s = fmaf(A[m*K+k], W[n*K+k], s);
    #pragma unroll
    for (int o = 16; o > 0; o >>= 1) s += __shfl_down_sync(0xffffffffu, s, o);
    if (lane == 0){
        s += bias[n];
        if (act) s = fmaxf(s, 0.f);
        C[m*N+n] = s;
    }
}

// ---------------- scorer3 (defaults path only, 16 rows) --------------------
__global__ void k_scorer3(const float* __restrict__ H2, const float* __restrict__ W3,
                          const float* __restrict__ b3, float* __restrict__ out, int M)
{
    int warp = threadIdx.x >> 5, lane = threadIdx.x & 31;
    int row = blockIdx.x * 8 + warp;
    if (row >= M) return;
    const float* h = H2 + (long long)row * (D_/2);
    float sum = 0.f;
    #pragma unroll
    for (int t = 0; t < 8; t++) sum = fmaf(h[lane + t*32], W3[lane + t*32], sum);
    #pragma unroll
    for (int o = 16; o > 0; o >>= 1) sum += __shfl_down_sync(0xffffffffu, sum, o);
    if (lane == 0) out[row] = tanhf(sum + b3[0]);
}

// ---------------- softmax (fb EMA inlined, row-offset): 128 thr/row --------
__global__ void __launch_bounds__(128)
k_softmax(const float* __restrict__ scores, float* __restrict__ wt,
          float* __restrict__ fbw, const void* __restrict__ maskp,
          const float* __restrict__ fallback, int row0)
{
    __shared__ float red[128];
    const int row = blockIdx.x + row0, b = row >> 10, g = threadIdx.x;
    const float* s = scores + (long long)row * LK_ + g*8;
    const int mode = g_maskmode;
    const float bmax = funmap(g_umax), bmin = funmap(g_umin);
    const float fb = 0.99f * fallback[0] + 0.01f * ((bmax + bmin) * 0.5f);

    float4 va = ((const float4*)s)[0];
    float4 vb = ((const float4*)s)[1];
    float x[8] = {va.x,va.y,va.z,va.w, vb.x,vb.y,vb.z,vb.w};
    int mk[8];
    const int mbase = b*LK_ + g*8;
    if (mode == 0){
        uchar4 a = ((const uchar4*)maskp)[(mbase>>2)];
        uchar4 c = ((const uchar4*)maskp)[(mbase>>2)+1];
        mk[0]=a.x!=0; mk[1]=a.y!=0; mk[2]=a.z!=0; mk[3]=a.w!=0;
        mk[4]=c.x!=0; mk[5]=c.y!=0; mk[6]=c.z!=0; mk[7]=c.w!=0;
    } else if (mode == 1){
        int4 a = ((const int4*)maskp)[(mbase>>2)];
        int4 c = ((const int4*)maskp)[(mbase>>2)+1];
        mk[0]=a.x!=0; mk[1]=a.y!=0; mk[2]=a.z!=0; mk[3]=a.w!=0;
        mk[4]=c.x!=0; mk[5]=c.y!=0; mk[6]=c.z!=0; mk[7]=c.w!=0;
    } else {
        float4 a = ((const float4*)maskp)[(mbase>>2)];
        float4 c = ((const float4*)maskp)[(mbase>>2)+1];
        mk[0]=a.x!=0.f; mk[1]=a.y!=0.f; mk[2]=a.z!=0.f; mk[3]=a.w!=0.f;
        mk[4]=c.x!=0.f; mk[5]=c.y!=0.f; mk[6]=c.z!=0.f; mk[7]=c.w!=0.f;
    }
    float lmax = fb;
    #pragma unroll
    for (int c = 0; c < 8; c++) if (!mk[c]) lmax = fmaxf(lmax, x[c]);
    red[g] = lmax; __syncthreads();
    for (int st = 64; st > 0; st >>= 1){
        if (g < st) red[g] = fmaxf(red[g], red[g+st]);
        __syncthreads();
    }
    const float m = red[0];
    __syncthreads();
    float e[8], lsum = 0.f;
    #pragma unroll
    for (int c = 0; c < 8; c++){ e[c] = mk[c] ? 0.f : expf(x[c]-m); lsum += e[c]; }
    red[g] = lsum; __syncthreads();
    for (int st = 64; st > 0; st >>= 1){
        if (g < st) red[g] += red[g+st];
        __syncthreads();
    }
    const float fbe = expf(fb - m);
    const float inv = 1.f / (red[0] + fbe);
    float* w = wt + (long long)row*LK_ + g*8;
    ((float4*)w)[0] = make_float4(tf32r(e[0]*inv), tf32r(e[4]*inv), tf32r(e[1]*inv), tf32r(e[5]*inv));
    ((float4*)w)[1] = make_float4(tf32r(e[2]*inv), tf32r(e[6]*inv), tf32r(e[3]*inv), tf32r(e[7]*inv));
    if (g == 0) fbw[row] = fbe * inv;
}

// ---------------------------------------------------------------------------
#define GA(p, sym) { void* _t; cudaGetSymbolAddress(&_t, sym); p = (float*)_t; }

extern "C" void kernel_launch(void* const* d_in, const int* in_sizes, int n_in,
                              void* d_out, int out_size)
{
    const float* uncond_q = (const float*)d_in[0];
    const float* q  = (const float*)d_in[1];
    const float* k  = (const float*)d_in[2];
    const float* v  = (const float*)d_in[3];
    const void*  mask = d_in[4];
    const float* fallback = (const float*)d_in[5];
    const float* Wv = (const float*)d_in[6];
    const float* bv = (const float*)d_in[7];
    const float* Wf = (const float*)d_in[8];
    const float* bf = (const float*)d_in[9];
    const float* W1 = (const float*)d_in[10];
    const float* b1 = (const float*)d_in[11];
    const float* W2 = (const float*)d_in[12];
    const float* b2 = (const float*)d_in[13];
    const float* W3 = (const float*)d_in[14];
    const float* b3 = (const float*)d_in[15];

    float *qp,*kp,*vpin,*wvp,*w1p,*w2p,*vpt,*scores,*wt,*attn,*h1;
    float *fbw,*defv,*dh1,*dh2;
    GA(qp,g_qp); GA(kp,g_kp); GA(vpin,g_vpin);
    GA(wvp,g_wvp); GA(w1p,g_w1p); GA(w2p,g_w2p);
    GA(vpt,g_vpt); GA(scores,g_scores); GA(wt,g_wt);
    GA(attn,g_attn); GA(h1,g_h1);
    GA(fbw,g_fbw); GA(defv,g_def); GA(dh1,g_dh1); GA(dh2,g_dh2);

    // one-time infra (created on the non-captured correctness call)
    static cudaStream_t s1 = nullptr, s2 = nullptr;
    static cudaEvent_t eF = nullptr, e1 = nullptr, e2 = nullptr, eK = nullptr;
    static cudaEvent_t eS[4] = {nullptr,nullptr,nullptr,nullptr};
    static cudaEvent_t eA = nullptr;
    if (!s1){
        cudaStreamCreateWithFlags(&s1, cudaStreamNonBlocking);
        cudaStreamCreateWithFlags(&s2, cudaStreamNonBlocking);
        cudaEventCreateWithFlags(&eF, cudaEventDisableTiming);
        cudaEventCreateWithFlags(&e1, cudaEventDisableTiming);
        cudaEventCreateWithFlags(&e2, cudaEventDisableTiming);
        cudaEventCreateWithFlags(&eK, cudaEventDisableTiming);
        cudaEventCreateWithFlags(&eA, cudaEventDisableTiming);
        for (int i = 0; i < 4; i++)
            cudaEventCreateWithFlags(&eS[i], cudaEventDisableTiming);
        cudaFuncSetAttribute(k6<0>, cudaFuncAttributeMaxDynamicSharedMemorySize, ENG_SMEM);
        cudaFuncSetAttribute(k6<2>, cudaFuncAttributeMaxDynamicSharedMemorySize, ENG_SMEM);
        cudaFuncSetAttribute(k6<3>, cudaFuncAttributeMaxDynamicSharedMemorySize, ENG_SMEM);
        cudaFuncSetAttribute(k6<5>, cudaFuncAttributeMaxDynamicSharedMemorySize, ENG_SMEM);
        cudaFuncSetAttribute(k6<6>, cudaFuncAttributeMaxDynamicSharedMemorySize, ENG_SMEM);
    }

    const float inv_sqrt_d = 0.04419417382415922f;
    const long long sQ = (long long)LQ_*D_;
    const long long sS = (long long)LQ_*LK_;
    const long long sVT = (long long)D_*LK_;
    float* out = (float*)d_out;
    const int do_out = (out_size >= NROW_ + B_) ? 1 : 0;

    // fork side streams from the main stream
    cudaEventRecord(eF, 0);
    cudaStreamWaitEvent(s1, eF, 0);
    cudaStreamWaitEvent(s2, eF, 0);

    // ---- s1: v convert + weight converts + vp GEMM ----
    k_cvt1<<<8192, 256, 0, s1>>>((const float4*)v, vpin, NROW_*D_/4);
    k_cvt3<<<dim3(256,3), 256, 0, s1>>>((const float4*)Wv, wvp, (const float4*)W1, w1p,
                                        (const float4*)W2, w2p,
                                        D_*D_/4, D_*D_/4, (D_/2)*D_/4);
    k6<5><<<dim3(2,128,1), 256, ENG_SMEM, s1>>>(vpin, wvp, bv, vpt,
        D_, D_, 0, 0, 0, 1.f, nullptr, nullptr, 0);
    cudaEventRecord(e1, s1);

    // ---- s2: cvt(k) off the critical path, then defaults ----
    k_cvt1<<<8192, 256, 0, s2>>>((const float4*)k, kp, NROW_*D_/4);
    cudaEventRecord(eK, s2);
    k_small<<<(B_*D_+7)/8, 256, 0, s2>>>(uncond_q, Wf, bf, defv, B_, D_, D_, 0);
    k_small<<<(B_*D_+7)/8, 256, 0, s2>>>(defv, W1, b1, dh1, B_, D_, D_, 1);
    k_small<<<(B_*(D_/2)+7)/8, 256, 0, s2>>>(dh1, W2, b2, dh2, B_, D_/2, D_, 1);
    if (do_out)
        k_scorer3<<<2, 256, 0, s2>>>(dh2, W3, b3, out + NROW_, B_);
    cudaEventRecord(e2, s2);

    // ---- main stream: QK chain ----
    k_init_detect<<<1, 256>>>((const unsigned char*)mask);
    k_cvt1<<<8192, 256>>>((const float4*)q, qp, NROW_*D_/4);
    cudaStreamWaitEvent(0, eK, 0);

    k6<0><<<dim3(4,8,B_), 256, ENG_SMEM>>>(qp, kp, nullptr, scores,
        LK_, D_, sQ, sQ, sS, inv_sqrt_d, nullptr, nullptr, 0);

    // ---- pipelined softmax (main) -> attn (s1) in 4 batch-groups ----
    // attn on s1 follows vp GEMM (program order) and waits defv (e2) once.
    cudaStreamWaitEvent(s1, e2, 0);
    for (int gidx = 0; gidx < 4; gidx++){
        k_softmax<<<4096, 128>>>(scores, wt, fbw, mask, fallback, gidx*4096);
        cudaEventRecord(eS[gidx], 0);
        cudaStreamWaitEvent(s1, eS[gidx], 0);
        k6<2><<<dim3(2,8,4), 256, ENG_SMEM, s1>>>(wt, vpt, nullptr, attn,
            D_, LK_, sS, sVT, sQ, 1.f, fbw, defv, gidx*4);
    }
    cudaEventRecord(eA, s1);
    cudaStreamWaitEvent(0, eA, 0);

    // h1 = relu(attn @ W1^T + b1) -> rounded+permuted
    k6<3><<<dim3(2,128,1), 256, ENG_SMEM>>>(attn, w1p, b1, h1,
        D_, D_, 0, 0, 0, 1.f, nullptr, nullptr, 0);

    // fused: h2 = relu(h1 @ W2^T + b2); out = tanh(h2 . W3 + b3)
    k6<6><<<dim3(1,128,1), 256, ENG_SMEM>>>(h1, w2p, b2, out,
        D_/2, D_, 0, 0, 0, 1.f, W3, b3, 0);
}

// round 13
// speedup vs baseline: 1.2256x; 1.2256x over previous
#include <cuda_runtime.h>
#include <math.h>
#include <stdint.h>

#define D_ 512
#define B_ 16
#define LQ_ 1024
#define LK_ 1024
#define NROW_ (B_*LQ_)

// ---------------- scratch globals (tf32-rounded, k-permuted planes) --------
__device__ __align__(16) float g_qp[NROW_*D_];
__device__ __align__(16) float g_kp[NROW_*D_];
__device__ __align__(16) float g_vpin[NROW_*D_];
__device__ __align__(16) float g_wvp[D_*D_];
__device__ __align__(16) float g_w1p[D_*D_];
__device__ __align__(16) float g_w2p[(D_/2)*D_];
__device__ __align__(16) float g_vpt[B_*D_*LK_];
__device__ __align__(16) float g_scores[(long long)B_*LQ_*LK_];
__device__ __align__(16) float g_wt[(long long)B_*LQ_*LK_];
__device__ __align__(16) float g_attn[NROW_*D_];
__device__ __align__(16) float g_h1[NROW_*D_];
__device__ float g_fbw[NROW_];
__device__ float g_def[B_*D_], g_dh1[B_*D_], g_dh2[B_*(D_/2)];
__device__ unsigned g_umax, g_umin;
__device__ int g_maskmode;

// ---------------- helpers ---------------------------------------------------
__device__ __forceinline__ unsigned fmap(float f){
    unsigned u = __float_as_uint(f);
    return (u & 0x80000000u) ? ~u : (u | 0x80000000u);
}
__device__ __forceinline__ float funmap(unsigned m){
    return (m & 0x80000000u) ? __uint_as_float(m ^ 0x80000000u) : __uint_as_float(~m);
}
__device__ __forceinline__ float tf32r(float x){
    unsigned r; asm("cvt.rna.tf32.f32 %0, %1;" : "=r"(r) : "f"(x));
    return __uint_as_float(r);
}
__device__ __forceinline__ int kperm(int c){
    return (c & ~7) | ((c & 3) << 1) | ((c >> 2) & 1);
}
#define CPA16(sa, gp) asm volatile("cp.async.cg.shared.global [%0], [%1], 16;\n" :: "r"(sa), "l"(gp))
#define CPA_COMMIT() asm volatile("cp.async.commit_group;\n" ::: "memory")
#define CPA_WAIT1()  asm volatile("cp.async.wait_group 1;\n" ::: "memory")

#define MMA_TF32(acc, a0, a1, a2, a3, b0, b1) \
    asm volatile( \
        "mma.sync.aligned.m16n8k8.row.col.f32.tf32.tf32.f32 " \
        "{%0,%1,%2,%3}, {%4,%5,%6,%7}, {%8,%9}, {%0,%1,%2,%3};" \
        : "+f"((acc)[0]), "+f"((acc)[1]), "+f"((acc)[2]), "+f"((acc)[3]) \
        : "r"(a0), "r"(a1), "r"(a2), "r"(a3), "r"(b0), "r"(b1))

// ---------------- init + mask dtype detection ------------------------------
__global__ void k_init_detect(const unsigned char* __restrict__ mb){
    __shared__ int sGE2, sOff;
    int tid = threadIdx.x;
    if (tid == 0){ sGE2 = 0; sOff = 0; g_umax = 0u; g_umin = 0xFFFFFFFFu; }
    __syncthreads();
    int ge2 = 0, off = 0;
    for (int i = tid; i < B_*LK_; i += blockDim.x){
        unsigned char c = mb[i];
        if (c > 1) ge2 = 1;
        else if (c == 1 && (i & 3)) off = 1;
    }
    if (ge2) sGE2 = 1;
    if (off) sOff = 1;
    __syncthreads();
    if (tid == 0) g_maskmode = sGE2 ? 2 : (sOff ? 0 : 1);
}

// ---------------- converts: f32 -> tf32-rounded, k-permuted ----------------
__device__ __forceinline__ void cvt4(const float4* x, float* y, int i){
    float4 v = x[i];
    int base = i * 4;
    y[kperm(base  )] = tf32r(v.x);
    y[kperm(base+1)] = tf32r(v.y);
    y[kperm(base+2)] = tf32r(v.z);
    y[kperm(base+3)] = tf32r(v.w);
}
__global__ void k_cvt1(const float4* __restrict__ x, float* __restrict__ y, int n4){
    int i = blockIdx.x * blockDim.x + threadIdx.x;
    if (i < n4) cvt4(x, y, i);
}
__global__ void k_cvt3(const float4* __restrict__ x0, float* __restrict__ y0,
                       const float4* __restrict__ x1, float* __restrict__ y1,
                       const float4* __restrict__ x2, float* __restrict__ y2,
                       int n40, int n41, int n42){
    int i = blockIdx.x * blockDim.x + threadIdx.x;
    int z = blockIdx.y;
    if (z == 0){ if (i < n40) cvt4(x0, y0, i); }
    else if (z == 1){ if (i < n41) cvt4(x1, y1, i); }
    else { if (i < n42) cvt4(x2, y2, i); }
}

// =================== tf32 mma.sync NT GEMM engine (round-7 best) ===========
#define ASTR 40
#define AW (128*ASTR)
#define BW (256*ASTR)
#define STGW (AW+BW)
#define ENG_SMEM (3*STGW*4)

template<int EPI>
__global__ void __launch_bounds__(256, 1)
k6(const float* __restrict__ A, const float* __restrict__ Bm,
   const float* __restrict__ bias, float* __restrict__ C,
   int N, int K, long long sA, long long sB, long long sC, float scale,
   const float* __restrict__ fbw, const float* __restrict__ defv)
{
    extern __shared__ float dsm[];
    __shared__ float red[512];

    const int bz = blockIdx.z;
    A  += (long long)bz * sA;
    Bm += (long long)bz * sB;
    C  += (long long)bz * sC;

    const int m0 = blockIdx.y * 128, n0 = blockIdx.x * 256;
    const int tid = threadIdx.x, lane = tid & 31, warp = tid >> 5;
    const int rbase = (warp & 1) * 64;
    const int cbase = (warp >> 1) * 64;
    const int grp = lane >> 2, qd = lane & 3;

    float* As = dsm;
    float* Bs = dsm + 3*AW;
    const unsigned asu = (unsigned)__cvta_generic_to_shared(As);
    const unsigned bsu = (unsigned)__cvta_generic_to_shared(Bs);

    const int niter = K >> 5;

    auto load_stage = [&](int g){
        const int buf = g % 3;
        const int k0 = g << 5;
        const unsigned ab = asu + buf * (AW*4);
        const unsigned bb = bsu + buf * (BW*4);
        #pragma unroll
        for (int i = 0; i < 4; i++){
            int id = tid + 256*i, row = id >> 3, ch = (id & 7) * 4;
            CPA16(ab + (unsigned)(row*ASTR + ch)*4,
                  A + (long long)(m0 + row)*K + k0 + ch);
        }
        #pragma unroll
        for (int i = 0; i < 8; i++){
            int id = tid + 256*i, row = id >> 3, ch = (id & 7) * 4;
            CPA16(bb + (unsigned)(row*ASTR + ch)*4,
                  Bm + (long long)(n0 + row)*K + k0 + ch);
        }
    };

    float acc[4][8][4];
    #pragma unroll
    for (int mt = 0; mt < 4; mt++)
        #pragma unroll
        for (int u = 0; u < 8; u++)
            #pragma unroll
            for (int r = 0; r < 4; r++) acc[mt][u][r] = 0.f;

    load_stage(0); CPA_COMMIT();
    load_stage(1); CPA_COMMIT();

    for (int it = 0; it < niter; ++it){
        CPA_WAIT1();
        __syncthreads();
        const float* As_s = As + (it % 3)*AW;
        const float* Bs_s = Bs + (it % 3)*BW;
        #pragma unroll
        for (int kk = 0; kk < 32; kk += 8){
            uint2 aLo[4], aHi[4], bF[8];
            #pragma unroll
            for (int mt = 0; mt < 4; mt++){
                const int m = rbase + mt*16 + grp;
                aLo[mt] = *(const uint2*)&As_s[m*ASTR + kk + 2*qd];
                aHi[mt] = *(const uint2*)&As_s[(m+8)*ASTR + kk + 2*qd];
            }
            #pragma unroll
            for (int u = 0; u < 8; u++){
                const int n = cbase + u*8 + grp;
                bF[u] = *(const uint2*)&Bs_s[n*ASTR + kk + 2*qd];
            }
            #pragma unroll
            for (int mt = 0; mt < 4; mt++)
                #pragma unroll
                for (int u = 0; u < 8; u++)
                    MMA_TF32(acc[mt][u], aLo[mt].x, aHi[mt].x, aLo[mt].y, aHi[mt].y,
                             bF[u].x, bF[u].y);
        }
        __syncthreads();
        if (it + 2 < niter) load_stage(it + 2);
        CPA_COMMIT();
    }

    if (EPI == 0){
        float lmax = -INFINITY, lmin = INFINITY;
        #pragma unroll
        for (int mt = 0; mt < 4; mt++){
            const int row = m0 + rbase + mt*16 + grp;
            #pragma unroll
            for (int u = 0; u < 8; u++){
                const int col = n0 + cbase + u*8 + qd*2;
                float v0 = acc[mt][u][0]*scale, v1 = acc[mt][u][1]*scale;
                float v2 = acc[mt][u][2]*scale, v3 = acc[mt][u][3]*scale;
                lmax = fmaxf(fmaxf(lmax, fmaxf(v0,v1)), fmaxf(v2,v3));
                lmin = fminf(fminf(lmin, fminf(v0,v1)), fminf(v2,v3));
                *(float2*)(C + (long long)row*N + col)     = make_float2(v0, v1);
                *(float2*)(C + (long long)(row+8)*N + col) = make_float2(v2, v3);
            }
        }
        red[tid] = lmax; red[256+tid] = lmin;
        __syncthreads();
        for (int st = 128; st > 0; st >>= 1){
            if (tid < st){
                red[tid]     = fmaxf(red[tid],     red[tid+st]);
                red[256+tid] = fminf(red[256+tid], red[256+tid+st]);
            }
            __syncthreads();
        }
        if (tid == 0){
            atomicMax(&g_umax, fmap(red[0]));
            atomicMin(&g_umin, fmap(red[256]));
        }
    } else if (EPI == 2 || EPI == 3){
        #pragma unroll
        for (int mt = 0; mt < 4; mt++){
            const int row = m0 + rbase + mt*16 + grp;
            float fw0 = 0.f, fw1 = 0.f;
            if (EPI == 2){ fw0 = fbw[bz*LQ_ + row]; fw1 = fbw[bz*LQ_ + row + 8]; }
            #pragma unroll
            for (int u = 0; u < 8; u++){
                const int col = n0 + cbase + u*8 + qd*2;
                float v0 = acc[mt][u][0], v1 = acc[mt][u][1];
                float v2 = acc[mt][u][2], v3 = acc[mt][u][3];
                const int p0 = n0 + cbase + u*8 + kperm(qd*2);
                const int p1 = n0 + cbase + u*8 + kperm(qd*2 + 1);
                if (EPI == 2){
                    float d0 = defv[bz*D_ + col], d1 = defv[bz*D_ + col + 1];
                    C[(long long)row*N + p0]     = tf32r(v0 + fw0*d0);
                    C[(long long)row*N + p1]     = tf32r(v1 + fw0*d1);
                    C[(long long)(row+8)*N + p0] = tf32r(v2 + fw1*d0);
                    C[(long long)(row+8)*N + p1] = tf32r(v3 + fw1*d1);
                } else {
                    float b0 = bias[col], b1 = bias[col+1];
                    C[(long long)row*N + p0]     = tf32r(fmaxf(v0 + b0, 0.f));
                    C[(long long)row*N + p1]     = tf32r(fmaxf(v1 + b1, 0.f));
                    C[(long long)(row+8)*N + p0] = tf32r(fmaxf(v2 + b0, 0.f));
                    C[(long long)(row+8)*N + p1] = tf32r(fmaxf(v3 + b1, 0.f));
                }
            }
        }
    } else if (EPI == 5){
        #pragma unroll
        for (int mt = 0; mt < 4; mt++){
            const int r0 = m0 + rbase + mt*16 + grp;
            const int r1 = r0 + 8;
            const int b0i = r0 >> 10, l0i = r0 & 1023;
            const int b1i = r1 >> 10, l1i = r1 & 1023;
            const long long o0 = (long long)b0i*D_*LK_ + kperm(l0i);
            const long long o1 = (long long)b1i*D_*LK_ + kperm(l1i);
            #pragma unroll
            for (int u = 0; u < 8; u++){
                const int col = n0 + cbase + u*8 + qd*2;
                const float bb0 = bias[col], bb1 = bias[col+1];
                C[o0 + (long long)col*LK_]     = tf32r(acc[mt][u][0] + bb0);
                C[o0 + (long long)(col+1)*LK_] = tf32r(acc[mt][u][1] + bb1);
                C[o1 + (long long)col*LK_]     = tf32r(acc[mt][u][2] + bb0);
                C[o1 + (long long)(col+1)*LK_] = tf32r(acc[mt][u][3] + bb1);
            }
        }
    } else if (EPI == 6){
        float part[8];
        #pragma unroll
        for (int i = 0; i < 8; i++) part[i] = 0.f;
        #pragma unroll
        for (int u = 0; u < 8; u++){
            const int col = cbase + u*8 + qd*2;
            const float w0 = fbw[col], w1 = fbw[col+1];
            const float b0 = bias[col], b1 = bias[col+1];
            #pragma unroll
            for (int mt = 0; mt < 4; mt++){
                part[mt*2]   += fmaxf(acc[mt][u][0]+b0, 0.f)*w0 + fmaxf(acc[mt][u][1]+b1, 0.f)*w1;
                part[mt*2+1] += fmaxf(acc[mt][u][2]+b0, 0.f)*w0 + fmaxf(acc[mt][u][3]+b1, 0.f)*w1;
            }
        }
        #pragma unroll
        for (int i = 0; i < 8; i++){
            part[i] += __shfl_xor_sync(0xffffffffu, part[i], 1);
            part[i] += __shfl_xor_sync(0xffffffffu, part[i], 2);
        }
        if (qd == 0){
            const int cg = warp >> 1;
            #pragma unroll
            for (int mt = 0; mt < 4; mt++){
                red[(rbase + mt*16 + grp)*4 + cg]     = part[mt*2];
                red[(rbase + mt*16 + grp + 8)*4 + cg] = part[mt*2+1];
            }
        }
        __syncthreads();
        if (tid < 128){
            float s = red[tid*4] + red[tid*4+1] + red[tid*4+2] + red[tid*4+3];
            C[m0 + tid] = tanhf(s + defv[0]);
        }
    }
}

// ---------------- tiny SIMT GEMM (M=16 paths, raw f32) ---------------------
__global__ void k_small(const float* __restrict__ A, const float* __restrict__ W,
                        const float* __restrict__ bias, float* __restrict__ C,
                        int M, int N, int K, int act)
{
    int g = blockIdx.x*8 + (threadIdx.x>>5), lane = threadIdx.x & 31;
    int m = g / N, n = g % N;
    if (m >= M) return;
    float s = 0.f;
    for (int k = lane; k < K; k += 32) s = fmaf(A[m*K+k], W[n*K+k], s);
    #pragma unroll
    for (int o = 16; o > 0; o >>= 1) s += __shfl_down_sync(0xffffffffu, s, o);
    if (lane == 0){
        s += bias[n];
        if (act) s = fmaxf(s, 0.f);
        C[m*N+n] = s;
    }
}

// ---------------- scorer3 (defaults path only, 16 rows) --------------------
__global__ void k_scorer3(const float* __restrict__ H2, const float* __restrict__ W3,
                          const float* __restrict__ b3, float* __restrict__ out, int M)
{
    int warp = threadIdx.x >> 5, lane = threadIdx.x & 31;
    int row = blockIdx.x * 8 + warp;
    if (row >= M) return;
    const float* h = H2 + (long long)row * (D_/2);
    float sum = 0.f;
    #pragma unroll
    for (int t = 0; t < 8; t++) sum = fmaf(h[lane + t*32], W3[lane + t*32], sum);
    #pragma unroll
    for (int o = 16; o > 0; o >>= 1) sum += __shfl_down_sync(0xffffffffu, sum, o);
    if (lane == 0) out[row] = tanhf(sum + b3[0]);
}

// ---------------- softmax (fb EMA inlined): 128 thr/row --------------------
__global__ void __launch_bounds__(128)
k_softmax(const float* __restrict__ scores, float* __restrict__ wt,
          float* __restrict__ fbw, const void* __restrict__ maskp,
          const float* __restrict__ fallback)
{
    __shared__ float red[128];
    const int row = blockIdx.x, b = row >> 10, g = threadIdx.x;
    const float* s = scores + (long long)row * LK_ + g*8;
    const int mode = g_maskmode;
    const float bmax = funmap(g_umax), bmin = funmap(g_umin);
    const float fb = 0.99f * fallback[0] + 0.01f * ((bmax + bmin) * 0.5f);

    float4 va = ((const float4*)s)[0];
    float4 vb = ((const float4*)s)[1];
    float x[8] = {va.x,va.y,va.z,va.w, vb.x,vb.y,vb.z,vb.w};
    int mk[8];
    const int mbase = b*LK_ + g*8;
    if (mode == 0){
        uchar4 a = ((const uchar4*)maskp)[(mbase>>2)];
        uchar4 c = ((const uchar4*)maskp)[(mbase>>2)+1];
        mk[0]=a.x!=0; mk[1]=a.y!=0; mk[2]=a.z!=0; mk[3]=a.w!=0;
        mk[4]=c.x!=0; mk[5]=c.y!=0; mk[6]=c.z!=0; mk[7]=c.w!=0;
    } else if (mode == 1){
        int4 a = ((const int4*)maskp)[(mbase>>2)];
        int4 c = ((const int4*)maskp)[(mbase>>2)+1];
        mk[0]=a.x!=0; mk[1]=a.y!=0; mk[2]=a.z!=0; mk[3]=a.w!=0;
        mk[4]=c.x!=0; mk[5]=c.y!=0; mk[6]=c.z!=0; mk[7]=c.w!=0;
    } else {
        float4 a = ((const float4*)maskp)[(mbase>>2)];
        float4 c = ((const float4*)maskp)[(mbase>>2)+1];
        mk[0]=a.x!=0.f; mk[1]=a.y!=0.f; mk[2]=a.z!=0.f; mk[3]=a.w!=0.f;
        mk[4]=c.x!=0.f; mk[5]=c.y!=0.f; mk[6]=c.z!=0.f; mk[7]=c.w!=0.f;
    }
    float lmax = fb;
    #pragma unroll
    for (int c = 0; c < 8; c++) if (!mk[c]) lmax = fmaxf(lmax, x[c]);
    red[g] = lmax; __syncthreads();
    for (int st = 64; st > 0; st >>= 1){
        if (g < st) red[g] = fmaxf(red[g], red[g+st]);
        __syncthreads();
    }
    const float m = red[0];
    __syncthreads();
    float e[8], lsum = 0.f;
    #pragma unroll
    for (int c = 0; c < 8; c++){ e[c] = mk[c] ? 0.f : expf(x[c]-m); lsum += e[c]; }
    red[g] = lsum; __syncthreads();
    for (int st = 64; st > 0; st >>= 1){
        if (g < st) red[g] += red[g+st];
        __syncthreads();
    }
    const float fbe = expf(fb - m);
    const float inv = 1.f / (red[0] + fbe);
    float* w = wt + (long long)row*LK_ + g*8;
    ((float4*)w)[0] = make_float4(tf32r(e[0]*inv), tf32r(e[4]*inv), tf32r(e[1]*inv), tf32r(e[5]*inv));
    ((float4*)w)[1] = make_float4(tf32r(e[2]*inv), tf32r(e[6]*inv), tf32r(e[3]*inv), tf32r(e[7]*inv));
    if (g == 0) fbw[row] = fbe * inv;
}

// ---------------------------------------------------------------------------
#define GA(p, sym) { void* _t; cudaGetSymbolAddress(&_t, sym); p = (float*)_t; }

extern "C" void kernel_launch(void* const* d_in, const int* in_sizes, int n_in,
                              void* d_out, int out_size)
{
    const float* uncond_q = (const float*)d_in[0];
    const float* q  = (const float*)d_in[1];
    const float* k  = (const float*)d_in[2];
    const float* v  = (const float*)d_in[3];
    const void*  mask = d_in[4];
    const float* fallback = (const float*)d_in[5];
    const float* Wv = (const float*)d_in[6];
    const float* bv = (const float*)d_in[7];
    const float* Wf = (const float*)d_in[8];
    const float* bf = (const float*)d_in[9];
    const float* W1 = (const float*)d_in[10];
    const float* b1 = (const float*)d_in[11];
    const float* W2 = (const float*)d_in[12];
    const float* b2 = (const float*)d_in[13];
    const float* W3 = (const float*)d_in[14];
    const float* b3 = (const float*)d_in[15];

    float *qp,*kp,*vpin,*wvp,*w1p,*w2p,*vpt,*scores,*wt,*attn,*h1;
    float *fbw,*defv,*dh1,*dh2;
    GA(qp,g_qp); GA(kp,g_kp); GA(vpin,g_vpin);
    GA(wvp,g_wvp); GA(w1p,g_w1p); GA(w2p,g_w2p);
    GA(vpt,g_vpt); GA(scores,g_scores); GA(wt,g_wt);
    GA(attn,g_attn); GA(h1,g_h1);
    GA(fbw,g_fbw); GA(defv,g_def); GA(dh1,g_dh1); GA(dh2,g_dh2);

    // one-time infra (created on the non-captured correctness call)
    static cudaStream_t s1 = nullptr, s2 = nullptr;
    static cudaEvent_t eF = nullptr, e1 = nullptr, e2 = nullptr, eK = nullptr;
    if (!s1){
        cudaStreamCreateWithFlags(&s1, cudaStreamNonBlocking);
        cudaStreamCreateWithFlags(&s2, cudaStreamNonBlocking);
        cudaEventCreateWithFlags(&eF, cudaEventDisableTiming);
        cudaEventCreateWithFlags(&e1, cudaEventDisableTiming);
        cudaEventCreateWithFlags(&e2, cudaEventDisableTiming);
        cudaEventCreateWithFlags(&eK, cudaEventDisableTiming);
        cudaFuncSetAttribute(k6<0>, cudaFuncAttributeMaxDynamicSharedMemorySize, ENG_SMEM);
        cudaFuncSetAttribute(k6<2>, cudaFuncAttributeMaxDynamicSharedMemorySize, ENG_SMEM);
        cudaFuncSetAttribute(k6<3>, cudaFuncAttributeMaxDynamicSharedMemorySize, ENG_SMEM);
        cudaFuncSetAttribute(k6<5>, cudaFuncAttributeMaxDynamicSharedMemorySize, ENG_SMEM);
        cudaFuncSetAttribute(k6<6>, cudaFuncAttributeMaxDynamicSharedMemorySize, ENG_SMEM);
    }

    const float inv_sqrt_d = 0.04419417382415922f;
    const long long sQ = (long long)LQ_*D_;
    const long long sS = (long long)LQ_*LK_;
    const long long sVT = (long long)D_*LK_;
    float* out = (float*)d_out;
    const int do_out = (out_size >= NROW_ + B_) ? 1 : 0;

    // fork side streams from the main stream
    cudaEventRecord(eF, 0);
    cudaStreamWaitEvent(s1, eF, 0);
    cudaStreamWaitEvent(s2, eF, 0);

    // ---- s1: v convert + weight converts + vp GEMM ----
    k_cvt1<<<8192, 256, 0, s1>>>((const float4*)v, vpin, NROW_*D_/4);
    k_cvt3<<<dim3(256,3), 256, 0, s1>>>((const float4*)Wv, wvp, (const float4*)W1, w1p,
                                        (const float4*)W2, w2p,
                                        D_*D_/4, D_*D_/4, (D_/2)*D_/4);
    k6<5><<<dim3(2,128,1), 256, ENG_SMEM, s1>>>(vpin, wvp, bv, vpt,
        D_, D_, 0, 0, 0, 1.f, nullptr, nullptr);
    cudaEventRecord(e1, s1);

    // ---- s2: cvt(k) off the critical path, then defaults ----
    k_cvt1<<<8192, 256, 0, s2>>>((const float4*)k, kp, NROW_*D_/4);
    cudaEventRecord(eK, s2);
    k_small<<<(B_*D_+7)/8, 256, 0, s2>>>(uncond_q, Wf, bf, defv, B_, D_, D_, 0);
    k_small<<<(B_*D_+7)/8, 256, 0, s2>>>(defv, W1, b1, dh1, B_, D_, D_, 1);
    k_small<<<(B_*(D_/2)+7)/8, 256, 0, s2>>>(dh1, W2, b2, dh2, B_, D_/2, D_, 1);
    if (do_out)
        k_scorer3<<<2, 256, 0, s2>>>(dh2, W3, b3, out + NROW_, B_);
    cudaEventRecord(e2, s2);

    // ---- main stream: QK chain ----
    k_init_detect<<<1, 256>>>((const unsigned char*)mask);
    k_cvt1<<<8192, 256>>>((const float4*)q, qp, NROW_*D_/4);
    cudaStreamWaitEvent(0, eK, 0);

    k6<0><<<dim3(4,8,B_), 256, ENG_SMEM>>>(qp, kp, nullptr, scores,
        LK_, D_, sQ, sQ, sS, inv_sqrt_d, nullptr, nullptr);

    k_softmax<<<NROW_, 128>>>(scores, wt, fbw, mask, fallback);

    // join side streams before attn (needs vpt + defv; h1/W2 need w1p/w2p)
    cudaStreamWaitEvent(0, e1, 0);
    cudaStreamWaitEvent(0, e2, 0);

    k6<2><<<dim3(2,8,B_), 256, ENG_SMEM>>>(wt, vpt, nullptr, attn,
        D_, LK_, sS, sVT, sQ, 1.f, fbw, defv);

    k6<3><<<dim3(2,128,1), 256, ENG_SMEM>>>(attn, w1p, b1, h1,
        D_, D_, 0, 0, 0, 1.f, nullptr, nullptr);

    k6<6><<<dim3(1,128,1), 256, ENG_SMEM>>>(h1, w2p, b2, out,
        D_/2, D_, 0, 0, 0, 1.f, W3, b3);
}

// round 14
// speedup vs baseline: 1.2565x; 1.0253x over previous
#include <cuda_runtime.h>
#include <math.h>
#include <stdint.h>

#define D_ 512
#define B_ 16
#define LQ_ 1024
#define LK_ 1024
#define NROW_ (B_*LQ_)

// ---------------- scratch globals (tf32-rounded, k-permuted planes) --------
__device__ __align__(16) float g_qp[NROW_*D_];
__device__ __align__(16) float g_kp[NROW_*D_];
__device__ __align__(16) float g_vpin[NROW_*D_];
__device__ __align__(16) float g_wvp[D_*D_];
__device__ __align__(16) float g_w1p[D_*D_];
__device__ __align__(16) float g_w2p[(D_/2)*D_];
__device__ __align__(16) float g_vpt[B_*D_*LK_];
__device__ __align__(16) float g_scores[(long long)B_*LQ_*LK_];
__device__ __align__(16) float g_wt[(long long)B_*LQ_*LK_];
__device__ __align__(16) float g_attn[NROW_*D_];
__device__ __align__(16) float g_h1[NROW_*D_];
__device__ __align__(16) float g_h2[NROW_*(D_/2)];
__device__ float g_fbw[NROW_];
__device__ float g_def[B_*D_], g_dh1[B_*D_], g_dh2[B_*(D_/2)];
__device__ unsigned g_umax, g_umin;
__device__ int g_maskmode;

// ---------------- helpers ---------------------------------------------------
__device__ __forceinline__ unsigned fmap(float f){
    unsigned u = __float_as_uint(f);
    return (u & 0x80000000u) ? ~u : (u | 0x80000000u);
}
__device__ __forceinline__ float funmap(unsigned m){
    return (m & 0x80000000u) ? __uint_as_float(m ^ 0x80000000u) : __uint_as_float(~m);
}
__device__ __forceinline__ float tf32r(float x){
    unsigned r; asm("cvt.rna.tf32.f32 %0, %1;" : "=r"(r) : "f"(x));
    return __uint_as_float(r);
}
__device__ __forceinline__ int kperm(int c){
    return (c & ~7) | ((c & 3) << 1) | ((c >> 2) & 1);
}
#define CPA16(sa, gp) asm volatile("cp.async.cg.shared.global [%0], [%1], 16;\n" :: "r"(sa), "l"(gp))
#define CPA_COMMIT() asm volatile("cp.async.commit_group;\n" ::: "memory")
#define CPA_WAIT1()  asm volatile("cp.async.wait_group 1;\n" ::: "memory")

#define MMA_TF32(acc, a0, a1, a2, a3, b0, b1) \
    asm volatile( \
        "mma.sync.aligned.m16n8k8.row.col.f32.tf32.tf32.f32 " \
        "{%0,%1,%2,%3}, {%4,%5,%6,%7}, {%8,%9}, {%0,%1,%2,%3};" \
        : "+f"((acc)[0]), "+f"((acc)[1]), "+f"((acc)[2]), "+f"((acc)[3]) \
        : "r"(a0), "r"(a1), "r"(a2), "r"(a3), "r"(b0), "r"(b1))

// ---------------- init + mask dtype detection ------------------------------
__global__ void k_init_detect(const unsigned char* __restrict__ mb){
    __shared__ int sGE2, sOff;
    int tid = threadIdx.x;
    if (tid == 0){ sGE2 = 0; sOff = 0; g_umax = 0u; g_umin = 0xFFFFFFFFu; }
    __syncthreads();
    int ge2 = 0, off = 0;
    for (int i = tid; i < B_*LK_; i += blockDim.x){
        unsigned char c = mb[i];
        if (c > 1) ge2 = 1;
        else if (c == 1 && (i & 3)) off = 1;
    }
    if (ge2) sGE2 = 1;
    if (off) sOff = 1;
    __syncthreads();
    if (tid == 0) g_maskmode = sGE2 ? 2 : (sOff ? 0 : 1);
}

// ---------------- converts: f32 -> tf32-rounded, k-permuted ----------------
__device__ __forceinline__ void cvt4(const float4* x, float* y, int i){
    float4 v = x[i];
    int base = i * 4;
    y[kperm(base  )] = tf32r(v.x);
    y[kperm(base+1)] = tf32r(v.y);
    y[kperm(base+2)] = tf32r(v.z);
    y[kperm(base+3)] = tf32r(v.w);
}
__global__ void k_cvt1(const float4* __restrict__ x, float* __restrict__ y, int n4){
    int i = blockIdx.x * blockDim.x + threadIdx.x;
    if (i < n4) cvt4(x, y, i);
}
__global__ void k_cvt3(const float4* __restrict__ x0, float* __restrict__ y0,
                       const float4* __restrict__ x1, float* __restrict__ y1,
                       const float4* __restrict__ x2, float* __restrict__ y2,
                       int n40, int n41, int n42){
    int i = blockIdx.x * blockDim.x + threadIdx.x;
    int z = blockIdx.y;
    if (z == 0){ if (i < n40) cvt4(x0, y0, i); }
    else if (z == 1){ if (i < n41) cvt4(x1, y1, i); }
    else { if (i < n42) cvt4(x2, y2, i); }
}

// =================== tf32 mma.sync NT GEMM engine ==========================
// Tile 128(M) x 128(N), BK=32, 2-stage cp.async, 8 warps (2x4),
// warp tile 64x32, 2 CTAs/SM. Inputs tf32-rounded + k-permuted.
// EPI: 0 scale+minmax->f32 | 2 +fbw*def->perm-tf32 | 3 relu+bias->perm-tf32
//      4 relu+bias->f32 | 5 +bias -> vpt transposed+perm-tf32 [B][D][Lk]
#define ASTR 40
#define AW (128*ASTR)
#define BW (128*ASTR)
#define STGW (AW+BW)
#define ENG_SMEM (2*STGW*4)

template<int EPI>
__global__ void __launch_bounds__(256, 2)
k6(const float* __restrict__ A, const float* __restrict__ Bm,
   const float* __restrict__ bias, float* __restrict__ C,
   int N, int K, long long sA, long long sB, long long sC, float scale,
   const float* __restrict__ fbw, const float* __restrict__ defv)
{
    extern __shared__ float dsm[];
    __shared__ float red[512];

    const int bz = blockIdx.z;
    A  += (long long)bz * sA;
    Bm += (long long)bz * sB;
    C  += (long long)bz * sC;

    const int m0 = blockIdx.y * 128, n0 = blockIdx.x * 128;
    const int tid = threadIdx.x, lane = tid & 31, warp = tid >> 5;
    const int rbase = (warp & 1) * 64;       // M: 2 groups of 64
    const int cbase = (warp >> 1) * 32;      // N: 4 groups of 32
    const int grp = lane >> 2, qd = lane & 3;

    float* As = dsm;
    float* Bs = dsm + 2*AW;
    const unsigned asu = (unsigned)__cvta_generic_to_shared(As);
    const unsigned bsu = (unsigned)__cvta_generic_to_shared(Bs);

    const int niter = K >> 5;

    auto load_stage = [&](int g){
        const int buf = g & 1;
        const int k0 = g << 5;
        const unsigned ab = asu + buf * (AW*4);
        const unsigned bb = bsu + buf * (BW*4);
        #pragma unroll
        for (int i = 0; i < 4; i++){
            int id = tid + 256*i, row = id >> 3, ch = (id & 7) * 4;
            CPA16(ab + (unsigned)(row*ASTR + ch)*4,
                  A + (long long)(m0 + row)*K + k0 + ch);
            CPA16(bb + (unsigned)(row*ASTR + ch)*4,
                  Bm + (long long)(n0 + row)*K + k0 + ch);
        }
    };

    float acc[4][4][4];
    #pragma unroll
    for (int mt = 0; mt < 4; mt++)
        #pragma unroll
        for (int u = 0; u < 4; u++)
            #pragma unroll
            for (int r = 0; r < 4; r++) acc[mt][u][r] = 0.f;

    load_stage(0); CPA_COMMIT();
    load_stage(1); CPA_COMMIT();

    for (int it = 0; it < niter; ++it){
        CPA_WAIT1();
        __syncthreads();
        const float* As_s = As + (it & 1)*AW;
        const float* Bs_s = Bs + (it & 1)*BW;
        #pragma unroll
        for (int kk = 0; kk < 32; kk += 8){
            uint2 aLo[4], aHi[4], bF[4];
            #pragma unroll
            for (int mt = 0; mt < 4; mt++){
                const int m = rbase + mt*16 + grp;
                aLo[mt] = *(const uint2*)&As_s[m*ASTR + kk + 2*qd];
                aHi[mt] = *(const uint2*)&As_s[(m+8)*ASTR + kk + 2*qd];
            }
            #pragma unroll
            for (int u = 0; u < 4; u++){
                const int n = cbase + u*8 + grp;
                bF[u] = *(const uint2*)&Bs_s[n*ASTR + kk + 2*qd];
            }
            #pragma unroll
            for (int mt = 0; mt < 4; mt++)
                #pragma unroll
                for (int u = 0; u < 4; u++)
                    MMA_TF32(acc[mt][u], aLo[mt].x, aHi[mt].x, aLo[mt].y, aHi[mt].y,
                             bF[u].x, bF[u].y);
        }
        __syncthreads();
        if (it + 2 < niter) load_stage(it + 2);
        CPA_COMMIT();
    }

    if (EPI == 0){
        float lmax = -INFINITY, lmin = INFINITY;
        #pragma unroll
        for (int mt = 0; mt < 4; mt++){
            const int row = m0 + rbase + mt*16 + grp;
            #pragma unroll
            for (int u = 0; u < 4; u++){
                const int col = n0 + cbase + u*8 + qd*2;
                float v0 = acc[mt][u][0]*scale, v1 = acc[mt][u][1]*scale;
                float v2 = acc[mt][u][2]*scale, v3 = acc[mt][u][3]*scale;
                lmax = fmaxf(fmaxf(lmax, fmaxf(v0,v1)), fmaxf(v2,v3));
                lmin = fminf(fminf(lmin, fminf(v0,v1)), fminf(v2,v3));
                *(float2*)(C + (long long)row*N + col)     = make_float2(v0, v1);
                *(float2*)(C + (long long)(row+8)*N + col) = make_float2(v2, v3);
            }
        }
        red[tid] = lmax; red[256+tid] = lmin;
        __syncthreads();
        for (int st = 128; st > 0; st >>= 1){
            if (tid < st){
                red[tid]     = fmaxf(red[tid],     red[tid+st]);
                red[256+tid] = fminf(red[256+tid], red[256+tid+st]);
            }
            __syncthreads();
        }
        if (tid == 0){
            atomicMax(&g_umax, fmap(red[0]));
            atomicMin(&g_umin, fmap(red[256]));
        }
    } else if (EPI == 2 || EPI == 3){
        #pragma unroll
        for (int mt = 0; mt < 4; mt++){
            const int row = m0 + rbase + mt*16 + grp;
            float fw0 = 0.f, fw1 = 0.f;
            if (EPI == 2){ fw0 = fbw[bz*LQ_ + row]; fw1 = fbw[bz*LQ_ + row + 8]; }
            #pragma unroll
            for (int u = 0; u < 4; u++){
                const int col = n0 + cbase + u*8 + qd*2;
                float v0 = acc[mt][u][0], v1 = acc[mt][u][1];
                float v2 = acc[mt][u][2], v3 = acc[mt][u][3];
                const int p0 = n0 + cbase + u*8 + kperm(qd*2);
                const int p1 = n0 + cbase + u*8 + kperm(qd*2 + 1);
                if (EPI == 2){
                    float d0 = defv[bz*D_ + col], d1 = defv[bz*D_ + col + 1];
                    C[(long long)row*N + p0]     = tf32r(v0 + fw0*d0);
                    C[(long long)row*N + p1]     = tf32r(v1 + fw0*d1);
                    C[(long long)(row+8)*N + p0] = tf32r(v2 + fw1*d0);
                    C[(long long)(row+8)*N + p1] = tf32r(v3 + fw1*d1);
                } else {
                    float b0 = bias[col], b1 = bias[col+1];
                    C[(long long)row*N + p0]     = tf32r(fmaxf(v0 + b0, 0.f));
                    C[(long long)row*N + p1]     = tf32r(fmaxf(v1 + b1, 0.f));
                    C[(long long)(row+8)*N + p0] = tf32r(fmaxf(v2 + b0, 0.f));
                    C[(long long)(row+8)*N + p1] = tf32r(fmaxf(v3 + b1, 0.f));
                }
            }
        }
    } else if (EPI == 4){
        #pragma unroll
        for (int mt = 0; mt < 4; mt++){
            const int row = m0 + rbase + mt*16 + grp;
            #pragma unroll
            for (int u = 0; u < 4; u++){
                const int col = n0 + cbase + u*8 + qd*2;
                float b0 = bias[col], b1 = bias[col+1];
                *(float2*)(C + (long long)row*N + col) =
                    make_float2(fmaxf(acc[mt][u][0]+b0, 0.f), fmaxf(acc[mt][u][1]+b1, 0.f));
                *(float2*)(C + (long long)(row+8)*N + col) =
                    make_float2(fmaxf(acc[mt][u][2]+b0, 0.f), fmaxf(acc[mt][u][3]+b1, 0.f));
            }
        }
    } else if (EPI == 5){
        #pragma unroll
        for (int mt = 0; mt < 4; mt++){
            const int r0 = m0 + rbase + mt*16 + grp;
            const int r1 = r0 + 8;
            const int b0i = r0 >> 10, l0i = r0 & 1023;
            const int b1i = r1 >> 10, l1i = r1 & 1023;
            const long long o0 = (long long)b0i*D_*LK_ + kperm(l0i);
            const long long o1 = (long long)b1i*D_*LK_ + kperm(l1i);
            #pragma unroll
            for (int u = 0; u < 4; u++){
                const int col = n0 + cbase + u*8 + qd*2;
                const float bb0 = bias[col], bb1 = bias[col+1];
                C[o0 + (long long)col*LK_]     = tf32r(acc[mt][u][0] + bb0);
                C[o0 + (long long)(col+1)*LK_] = tf32r(acc[mt][u][1] + bb1);
                C[o1 + (long long)col*LK_]     = tf32r(acc[mt][u][2] + bb0);
                C[o1 + (long long)(col+1)*LK_] = tf32r(acc[mt][u][3] + bb1);
            }
        }
    }
}

// ---------------- tiny SIMT GEMM (M=16 paths, raw f32) ---------------------
__global__ void k_small(const float* __restrict__ A, const float* __restrict__ W,
                        const float* __restrict__ bias, float* __restrict__ C,
                        int M, int N, int K, int act)
{
    int g = blockIdx.x*8 + (threadIdx.x>>5), lane = threadIdx.x & 31;
    int m = g / N, n = g % N;
    if (m >= M) return;
    float s = 0.f;
    for (int k = lane; k < K; k += 32) s = fmaf(A[m*K+k], W[n*K+k], s);
    #pragma unroll
    for (int o = 16; o > 0; o >>= 1) s += __shfl_down_sync(0xffffffffu, s, o);
    if (lane == 0){
        s += bias[n];
        if (act) s = fmaxf(s, 0.f);
        C[m*N+n] = s;
    }
}

// ---------------- scorer3: tanh(h2 . W3 + b3) -------------------------------
__global__ void k_scorer3(const float* __restrict__ H2, const float* __restrict__ W3,
                          const float* __restrict__ b3, float* __restrict__ out, int M)
{
    int warp = threadIdx.x >> 5, lane = threadIdx.x & 31;
    int row = blockIdx.x * 8 + warp;
    if (row >= M) return;
    const float* h = H2 + (long long)row * (D_/2);
    float sum = 0.f;
    #pragma unroll
    for (int t = 0; t < 8; t++) sum = fmaf(h[lane + t*32], W3[lane + t*32], sum);
    #pragma unroll
    for (int o = 16; o > 0; o >>= 1) sum += __shfl_down_sync(0xffffffffu, sum, o);
    if (lane == 0) out[row] = tanhf(sum + b3[0]);
}

// ---------------- softmax (fb EMA inlined): 128 thr/row --------------------
__global__ void __launch_bounds__(128)
k_softmax(const float* __restrict__ scores, float* __restrict__ wt,
          float* __restrict__ fbw, const void* __restrict__ maskp,
          const float* __restrict__ fallback)
{
    __shared__ float red[128];
    const int row = blockIdx.x, b = row >> 10, g = threadIdx.x;
    const float* s = scores + (long long)row * LK_ + g*8;
    const int mode = g_maskmode;
    const float bmax = funmap(g_umax), bmin = funmap(g_umin);
    const float fb = 0.99f * fallback[0] + 0.01f * ((bmax + bmin) * 0.5f);

    float4 va = ((const float4*)s)[0];
    float4 vb = ((const float4*)s)[1];
    float x[8] = {va.x,va.y,va.z,va.w, vb.x,vb.y,vb.z,vb.w};
    int mk[8];
    const int mbase = b*LK_ + g*8;
    if (mode == 0){
        uchar4 a = ((const uchar4*)maskp)[(mbase>>2)];
        uchar4 c = ((const uchar4*)maskp)[(mbase>>2)+1];
        mk[0]=a.x!=0; mk[1]=a.y!=0; mk[2]=a.z!=0; mk[3]=a.w!=0;
        mk[4]=c.x!=0; mk[5]=c.y!=0; mk[6]=c.z!=0; mk[7]=c.w!=0;
    } else if (mode == 1){
        int4 a = ((const int4*)maskp)[(mbase>>2)];
        int4 c = ((const int4*)maskp)[(mbase>>2)+1];
        mk[0]=a.x!=0; mk[1]=a.y!=0; mk[2]=a.z!=0; mk[3]=a.w!=0;
        mk[4]=c.x!=0; mk[5]=c.y!=0; mk[6]=c.z!=0; mk[7]=c.w!=0;
    } else {
        float4 a = ((const float4*)maskp)[(mbase>>2)];
        float4 c = ((const float4*)maskp)[(mbase>>2)+1];
        mk[0]=a.x!=0.f; mk[1]=a.y!=0.f; mk[2]=a.z!=0.f; mk[3]=a.w!=0.f;
        mk[4]=c.x!=0.f; mk[5]=c.y!=0.f; mk[6]=c.z!=0.f; mk[7]=c.w!=0.f;
    }
    float lmax = fb;
    #pragma unroll
    for (int c = 0; c < 8; c++) if (!mk[c]) lmax = fmaxf(lmax, x[c]);
    red[g] = lmax; __syncthreads();
    for (int st = 64; st > 0; st >>= 1){
        if (g < st) red[g] = fmaxf(red[g], red[g+st]);
        __syncthreads();
    }
    const float m = red[0];
    __syncthreads();
    float e[8], lsum = 0.f;
    #pragma unroll
    for (int c = 0; c < 8; c++){ e[c] = mk[c] ? 0.f : expf(x[c]-m); lsum += e[c]; }
    red[g] = lsum; __syncthreads();
    for (int st = 64; st > 0; st >>= 1){
        if (g < st) red[g] += red[g+st];
        __syncthreads();
    }
    const float fbe = expf(fb - m);
    const float inv = 1.f / (red[0] + fbe);
    float* w = wt + (long long)row*LK_ + g*8;
    ((float4*)w)[0] = make_float4(tf32r(e[0]*inv), tf32r(e[4]*inv), tf32r(e[1]*inv), tf32r(e[5]*inv));
    ((float4*)w)[1] = make_float4(tf32r(e[2]*inv), tf32r(e[6]*inv), tf32r(e[3]*inv), tf32r(e[7]*inv));
    if (g == 0) fbw[row] = fbe * inv;
}

// ---------------------------------------------------------------------------
#define GA(p, sym) { void* _t; cudaGetSymbolAddress(&_t, sym); p = (float*)_t; }

extern "C" void kernel_launch(void* const* d_in, const int* in_sizes, int n_in,
                              void* d_out, int out_size)
{
    const float* uncond_q = (const float*)d_in[0];
    const float* q  = (const float*)d_in[1];
    const float* k  = (const float*)d_in[2];
    const float* v  = (const float*)d_in[3];
    const void*  mask = d_in[4];
    const float* fallback = (const float*)d_in[5];
    const float* Wv = (const float*)d_in[6];
    const float* bv = (const float*)d_in[7];
    const float* Wf = (const float*)d_in[8];
    const float* bf = (const float*)d_in[9];
    const float* W1 = (const float*)d_in[10];
    const float* b1 = (const float*)d_in[11];
    const float* W2 = (const float*)d_in[12];
    const float* b2 = (const float*)d_in[13];
    const float* W3 = (const float*)d_in[14];
    const float* b3 = (const float*)d_in[15];

    float *qp,*kp,*vpin,*wvp,*w1p,*w2p,*vpt,*scores,*wt,*attn,*h1,*h2;
    float *fbw,*defv,*dh1,*dh2;
    GA(qp,g_qp); GA(kp,g_kp); GA(vpin,g_vpin);
    GA(wvp,g_wvp); GA(w1p,g_w1p); GA(w2p,g_w2p);
    GA(vpt,g_vpt); GA(scores,g_scores); GA(wt,g_wt);
    GA(attn,g_attn); GA(h1,g_h1); GA(h2,g_h2);
    GA(fbw,g_fbw); GA(defv,g_def); GA(dh1,g_dh1); GA(dh2,g_dh2);

    static cudaStream_t s1 = nullptr, s2 = nullptr;
    static cudaEvent_t eF = nullptr, e1 = nullptr, e2 = nullptr, eK = nullptr;
    if (!s1){
        cudaStreamCreateWithFlags(&s1, cudaStreamNonBlocking);
        cudaStreamCreateWithFlags(&s2, cudaStreamNonBlocking);
        cudaEventCreateWithFlags(&eF, cudaEventDisableTiming);
        cudaEventCreateWithFlags(&e1, cudaEventDisableTiming);
        cudaEventCreateWithFlags(&e2, cudaEventDisableTiming);
        cudaEventCreateWithFlags(&eK, cudaEventDisableTiming);
        cudaFuncSetAttribute(k6<0>, cudaFuncAttributeMaxDynamicSharedMemorySize, ENG_SMEM);
        cudaFuncSetAttribute(k6<2>, cudaFuncAttributeMaxDynamicSharedMemorySize, ENG_SMEM);
        cudaFuncSetAttribute(k6<3>, cudaFuncAttributeMaxDynamicSharedMemorySize, ENG_SMEM);
        cudaFuncSetAttribute(k6<4>, cudaFuncAttributeMaxDynamicSharedMemorySize, ENG_SMEM);
        cudaFuncSetAttribute(k6<5>, cudaFuncAttributeMaxDynamicSharedMemorySize, ENG_SMEM);
    }

    const float inv_sqrt_d = 0.04419417382415922f;
    const long long sQ = (long long)LQ_*D_;
    const long long sS = (long long)LQ_*LK_;
    const long long sVT = (long long)D_*LK_;
    float* out = (float*)d_out;
    const int do_out = (out_size >= NROW_ + B_) ? 1 : 0;

    // fork side streams
    cudaEventRecord(eF, 0);
    cudaStreamWaitEvent(s1, eF, 0);
    cudaStreamWaitEvent(s2, eF, 0);

    // ---- s1: v convert + weight converts + vp GEMM ----
    k_cvt1<<<8192, 256, 0, s1>>>((const float4*)v, vpin, NROW_*D_/4);
    k_cvt3<<<dim3(256,3), 256, 0, s1>>>((const float4*)Wv, wvp, (const float4*)W1, w1p,
                                        (const float4*)W2, w2p,
                                        D_*D_/4, D_*D_/4, (D_/2)*D_/4);
    k6<5><<<dim3(4,128,1), 256, ENG_SMEM, s1>>>(vpin, wvp, bv, vpt,
        D_, D_, 0, 0, 0, 1.f, nullptr, nullptr);
    cudaEventRecord(e1, s1);

    // ---- s2: cvt(k) + defaults ----
    k_cvt1<<<8192, 256, 0, s2>>>((const float4*)k, kp, NROW_*D_/4);
    cudaEventRecord(eK, s2);
    k_small<<<(B_*D_+7)/8, 256, 0, s2>>>(uncond_q, Wf, bf, defv, B_, D_, D_, 0);
    k_small<<<(B_*D_+7)/8, 256, 0, s2>>>(defv, W1, b1, dh1, B_, D_, D_, 1);
    k_small<<<(B_*(D_/2)+7)/8, 256, 0, s2>>>(dh1, W2, b2, dh2, B_, D_/2, D_, 1);
    if (do_out)
        k_scorer3<<<2, 256, 0, s2>>>(dh2, W3, b3, out + NROW_, B_);
    cudaEventRecord(e2, s2);

    // ---- main stream: QK chain ----
    k_init_detect<<<1, 256>>>((const unsigned char*)mask);
    k_cvt1<<<8192, 256>>>((const float4*)q, qp, NROW_*D_/4);
    cudaStreamWaitEvent(0, eK, 0);

    k6<0><<<dim3(8,8,B_), 256, ENG_SMEM>>>(qp, kp, nullptr, scores,
        LK_, D_, sQ, sQ, sS, inv_sqrt_d, nullptr, nullptr);

    k_softmax<<<NROW_, 128>>>(scores, wt, fbw, mask, fallback);

    cudaStreamWaitEvent(0, e1, 0);
    cudaStreamWaitEvent(0, e2, 0);

    k6<2><<<dim3(4,8,B_), 256, ENG_SMEM>>>(wt, vpt, nullptr, attn,
        D_, LK_, sS, sVT, sQ, 1.f, fbw, defv);

    k6<3><<<dim3(4,128,1), 256, ENG_SMEM>>>(attn, w1p, b1, h1,
        D_, D_, 0, 0, 0, 1.f, nullptr, nullptr);

    k6<4><<<dim3(2,128,1), 256, ENG_SMEM>>>(h1, w2p, b2, h2,
        D_/2, D_, 0, 0, 0, 1.f, nullptr, nullptr);

    k_scorer3<<<NROW_/8, 256>>>(h2, W3, b3, out, NROW_);
}

// round 15
// speedup vs baseline: 1.2687x; 1.0097x over previous
#include <cuda_runtime.h>
#include <math.h>
#include <stdint.h>

#define D_ 512
#define B_ 16
#define LQ_ 1024
#define LK_ 1024
#define NROW_ (B_*LQ_)

// ---------------- scratch globals (tf32-rounded, k-permuted planes) --------
__device__ __align__(16) float g_qp[NROW_*D_];
__device__ __align__(16) float g_kp[NROW_*D_];
__device__ __align__(16) float g_vpin[NROW_*D_];
__device__ __align__(16) float g_wvp[D_*D_];
__device__ __align__(16) float g_w1p[D_*D_];
__device__ __align__(16) float g_w2p[(D_/2)*D_];
__device__ __align__(16) float g_vpt[B_*D_*LK_];
__device__ __align__(16) float g_scores[(long long)B_*LQ_*LK_];
__device__ __align__(16) float g_wt[(long long)B_*LQ_*LK_];
__device__ __align__(16) float g_attn[NROW_*D_];
__device__ __align__(16) float g_h1[NROW_*D_];
__device__ __align__(16) float g_outacc[NROW_];
__device__ float g_fbw[NROW_];
__device__ float g_def[B_*D_], g_dh1[B_*D_], g_dh2[B_*(D_/2)];
__device__ unsigned g_umax, g_umin;
__device__ int g_maskmode;

// ---------------- helpers ---------------------------------------------------
__device__ __forceinline__ unsigned fmap(float f){
    unsigned u = __float_as_uint(f);
    return (u & 0x80000000u) ? ~u : (u | 0x80000000u);
}
__device__ __forceinline__ float funmap(unsigned m){
    return (m & 0x80000000u) ? __uint_as_float(m ^ 0x80000000u) : __uint_as_float(~m);
}
__device__ __forceinline__ float tf32r(float x){
    unsigned r; asm("cvt.rna.tf32.f32 %0, %1;" : "=r"(r) : "f"(x));
    return __uint_as_float(r);
}
__device__ __forceinline__ int kperm(int c){
    return (c & ~7) | ((c & 3) << 1) | ((c >> 2) & 1);
}
#define CPA16(sa, gp) asm volatile("cp.async.cg.shared.global [%0], [%1], 16;\n" :: "r"(sa), "l"(gp))
#define CPA_COMMIT() asm volatile("cp.async.commit_group;\n" ::: "memory")
#define CPA_WAIT1()  asm volatile("cp.async.wait_group 1;\n" ::: "memory")

#define MMA_TF32(acc, a0, a1, a2, a3, b0, b1) \
    asm volatile( \
        "mma.sync.aligned.m16n8k8.row.col.f32.tf32.tf32.f32 " \
        "{%0,%1,%2,%3}, {%4,%5,%6,%7}, {%8,%9}, {%0,%1,%2,%3};" \
        : "+f"((acc)[0]), "+f"((acc)[1]), "+f"((acc)[2]), "+f"((acc)[3]) \
        : "r"(a0), "r"(a1), "r"(a2), "r"(a3), "r"(b0), "r"(b1))

// ---------------- init + mask dtype detection ------------------------------
__global__ void k_init_detect(const unsigned char* __restrict__ mb){
    __shared__ int sGE2, sOff;
    int tid = threadIdx.x;
    if (tid == 0){ sGE2 = 0; sOff = 0; g_umax = 0u; g_umin = 0xFFFFFFFFu; }
    __syncthreads();
    int ge2 = 0, off = 0;
    for (int i = tid; i < B_*LK_; i += blockDim.x){
        unsigned char c = mb[i];
        if (c > 1) ge2 = 1;
        else if (c == 1 && (i & 3)) off = 1;
    }
    if (ge2) sGE2 = 1;
    if (off) sOff = 1;
    __syncthreads();
    if (tid == 0) g_maskmode = sGE2 ? 2 : (sOff ? 0 : 1);
}

// ---------------- converts: f32 -> tf32-rounded, k-permuted ----------------
__device__ __forceinline__ void cvt4(const float4* x, float* y, int i){
    float4 v = x[i];
    int base = i * 4;
    y[kperm(base  )] = tf32r(v.x);
    y[kperm(base+1)] = tf32r(v.y);
    y[kperm(base+2)] = tf32r(v.z);
    y[kperm(base+3)] = tf32r(v.w);
}
__global__ void k_cvt1(const float4* __restrict__ x, float* __restrict__ y, int n4){
    int i = blockIdx.x * blockDim.x + threadIdx.x;
    if (i < n4) cvt4(x, y, i);
}
__global__ void k_cvt3(const float4* __restrict__ x0, float* __restrict__ y0,
                       const float4* __restrict__ x1, float* __restrict__ y1,
                       const float4* __restrict__ x2, float* __restrict__ y2,
                       int n40, int n41, int n42){
    int i = blockIdx.x * blockDim.x + threadIdx.x;
    int z = blockIdx.y;
    if (z == 0){ if (i < n40) cvt4(x0, y0, i); }
    else if (z == 1){ if (i < n41) cvt4(x1, y1, i); }
    else { if (i < n42) cvt4(x2, y2, i); }
}

// ---------------- zero the output accumulator ------------------------------
__global__ void k_zero(float* __restrict__ p, int n){
    int i = blockIdx.x * blockDim.x + threadIdx.x;
    if (i < n) p[i] = 0.f;
}
// ---------------- final tanh ------------------------------------------------
__global__ void k_tanh(const float* __restrict__ acc, const float* __restrict__ b3,
                       float* __restrict__ out, int n){
    int i = blockIdx.x * blockDim.x + threadIdx.x;
    if (i < n) out[i] = tanhf(acc[i] + b3[0]);
}

// =================== tf32 mma.sync NT GEMM engine ==========================
// Tile 128(M) x 128(N), BK=32, 2-stage cp.async, 8 warps (2x4),
// warp tile 64x32, 2 CTAs/SM. Inputs tf32-rounded + k-permuted.
// EPI: 0 scale+minmax->f32 | 2 +fbw*def->perm-tf32 | 3 relu+bias->perm-tf32
//      5 +bias -> vpt transposed+perm-tf32 [B][D][Lk]
//      7 relu+bias -> partial dot(W3) -> atomicAdd outacc[row]
#define ASTR 40
#define AW (128*ASTR)
#define BW (128*ASTR)
#define STGW (AW+BW)
#define ENG_SMEM (2*STGW*4)

template<int EPI>
__global__ void __launch_bounds__(256, 2)
k6(const float* __restrict__ A, const float* __restrict__ Bm,
   const float* __restrict__ bias, float* __restrict__ C,
   int N, int K, long long sA, long long sB, long long sC, float scale,
   const float* __restrict__ fbw, const float* __restrict__ defv)
{
    extern __shared__ float dsm[];
    __shared__ float red[512];

    const int bz = blockIdx.z;
    A  += (long long)bz * sA;
    Bm += (long long)bz * sB;
    C  += (long long)bz * sC;

    const int m0 = blockIdx.y * 128, n0 = blockIdx.x * 128;
    const int tid = threadIdx.x, lane = tid & 31, warp = tid >> 5;
    const int rbase = (warp & 1) * 64;
    const int cbase = (warp >> 1) * 32;
    const int grp = lane >> 2, qd = lane & 3;

    float* As = dsm;
    float* Bs = dsm + 2*AW;
    const unsigned asu = (unsigned)__cvta_generic_to_shared(As);
    const unsigned bsu = (unsigned)__cvta_generic_to_shared(Bs);

    const int niter = K >> 5;

    auto load_stage = [&](int g){
        const int buf = g & 1;
        const int k0 = g << 5;
        const unsigned ab = asu + buf * (AW*4);
        const unsigned bb = bsu + buf * (BW*4);
        #pragma unroll
        for (int i = 0; i < 4; i++){
            int id = tid + 256*i, row = id >> 3, ch = (id & 7) * 4;
            CPA16(ab + (unsigned)(row*ASTR + ch)*4,
                  A + (long long)(m0 + row)*K + k0 + ch);
            CPA16(bb + (unsigned)(row*ASTR + ch)*4,
                  Bm + (long long)(n0 + row)*K + k0 + ch);
        }
    };

    float acc[4][4][4];
    #pragma unroll
    for (int mt = 0; mt < 4; mt++)
        #pragma unroll
        for (int u = 0; u < 4; u++)
            #pragma unroll
            for (int r = 0; r < 4; r++) acc[mt][u][r] = 0.f;

    load_stage(0); CPA_COMMIT();
    load_stage(1); CPA_COMMIT();

    for (int it = 0; it < niter; ++it){
        CPA_WAIT1();
        __syncthreads();
        const float* As_s = As + (it & 1)*AW;
        const float* Bs_s = Bs + (it & 1)*BW;
        #pragma unroll
        for (int kk = 0; kk < 32; kk += 8){
            uint2 aLo[4], aHi[4], bF[4];
            #pragma unroll
            for (int mt = 0; mt < 4; mt++){
                const int m = rbase + mt*16 + grp;
                aLo[mt] = *(const uint2*)&As_s[m*ASTR + kk + 2*qd];
                aHi[mt] = *(const uint2*)&As_s[(m+8)*ASTR + kk + 2*qd];
            }
            #pragma unroll
            for (int u = 0; u < 4; u++){
                const int n = cbase + u*8 + grp;
                bF[u] = *(const uint2*)&Bs_s[n*ASTR + kk + 2*qd];
            }
            #pragma unroll
            for (int mt = 0; mt < 4; mt++)
                #pragma unroll
                for (int u = 0; u < 4; u++)
                    MMA_TF32(acc[mt][u], aLo[mt].x, aHi[mt].x, aLo[mt].y, aHi[mt].y,
                             bF[u].x, bF[u].y);
        }
        __syncthreads();
        if (it + 2 < niter) load_stage(it + 2);
        CPA_COMMIT();
    }

    if (EPI == 0){
        float lmax = -INFINITY, lmin = INFINITY;
        #pragma unroll
        for (int mt = 0; mt < 4; mt++){
            const int row = m0 + rbase + mt*16 + grp;
            #pragma unroll
            for (int u = 0; u < 4; u++){
                const int col = n0 + cbase + u*8 + qd*2;
                float v0 = acc[mt][u][0]*scale, v1 = acc[mt][u][1]*scale;
                float v2 = acc[mt][u][2]*scale, v3 = acc[mt][u][3]*scale;
                lmax = fmaxf(fmaxf(lmax, fmaxf(v0,v1)), fmaxf(v2,v3));
                lmin = fminf(fminf(lmin, fminf(v0,v1)), fminf(v2,v3));
                *(float2*)(C + (long long)row*N + col)     = make_float2(v0, v1);
                *(float2*)(C + (long long)(row+8)*N + col) = make_float2(v2, v3);
            }
        }
        red[tid] = lmax; red[256+tid] = lmin;
        __syncthreads();
        for (int st = 128; st > 0; st >>= 1){
            if (tid < st){
                red[tid]     = fmaxf(red[tid],     red[tid+st]);
                red[256+tid] = fminf(red[256+tid], red[256+tid+st]);
            }
            __syncthreads();
        }
        if (tid == 0){
            atomicMax(&g_umax, fmap(red[0]));
            atomicMin(&g_umin, fmap(red[256]));
        }
    } else if (EPI == 2 || EPI == 3){
        #pragma unroll
        for (int mt = 0; mt < 4; mt++){
            const int row = m0 + rbase + mt*16 + grp;
            float fw0 = 0.f, fw1 = 0.f;
            if (EPI == 2){ fw0 = fbw[bz*LQ_ + row]; fw1 = fbw[bz*LQ_ + row + 8]; }
            #pragma unroll
            for (int u = 0; u < 4; u++){
                const int col = n0 + cbase + u*8 + qd*2;
                float v0 = acc[mt][u][0], v1 = acc[mt][u][1];
                float v2 = acc[mt][u][2], v3 = acc[mt][u][3];
                const int p0 = n0 + cbase + u*8 + kperm(qd*2);
                const int p1 = n0 + cbase + u*8 + kperm(qd*2 + 1);
                if (EPI == 2){
                    float d0 = defv[bz*D_ + col], d1 = defv[bz*D_ + col + 1];
                    C[(long long)row*N + p0]     = tf32r(v0 + fw0*d0);
                    C[(long long)row*N + p1]     = tf32r(v1 + fw0*d1);
                    C[(long long)(row+8)*N + p0] = tf32r(v2 + fw1*d0);
                    C[(long long)(row+8)*N + p1] = tf32r(v3 + fw1*d1);
                } else {
                    float b0 = bias[col], b1 = bias[col+1];
                    C[(long long)row*N + p0]     = tf32r(fmaxf(v0 + b0, 0.f));
                    C[(long long)row*N + p1]     = tf32r(fmaxf(v1 + b1, 0.f));
                    C[(long long)(row+8)*N + p0] = tf32r(fmaxf(v2 + b0, 0.f));
                    C[(long long)(row+8)*N + p1] = tf32r(fmaxf(v3 + b1, 0.f));
                }
            }
        }
    } else if (EPI == 5){
        #pragma unroll
        for (int mt = 0; mt < 4; mt++){
            const int r0 = m0 + rbase + mt*16 + grp;
            const int r1 = r0 + 8;
            const int b0i = r0 >> 10, l0i = r0 & 1023;
            const int b1i = r1 >> 10, l1i = r1 & 1023;
            const long long o0 = (long long)b0i*D_*LK_ + kperm(l0i);
            const long long o1 = (long long)b1i*D_*LK_ + kperm(l1i);
            #pragma unroll
            for (int u = 0; u < 4; u++){
                const int col = n0 + cbase + u*8 + qd*2;
                const float bb0 = bias[col], bb1 = bias[col+1];
                C[o0 + (long long)col*LK_]     = tf32r(acc[mt][u][0] + bb0);
                C[o0 + (long long)(col+1)*LK_] = tf32r(acc[mt][u][1] + bb1);
                C[o1 + (long long)col*LK_]     = tf32r(acc[mt][u][2] + bb0);
                C[o1 + (long long)(col+1)*LK_] = tf32r(acc[mt][u][3] + bb1);
            }
        }
    } else if (EPI == 7){
        // relu(acc+bias) dot W3(=fbw) partial -> atomicAdd C[row] (C=outacc)
        float part[8];
        #pragma unroll
        for (int i = 0; i < 8; i++) part[i] = 0.f;
        #pragma unroll
        for (int u = 0; u < 4; u++){
            const int gcol = n0 + cbase + u*8 + qd*2;
            const float w0 = fbw[gcol], w1 = fbw[gcol+1];
            const float b0 = bias[gcol], b1 = bias[gcol+1];
            #pragma unroll
            for (int mt = 0; mt < 4; mt++){
                part[mt*2]   += fmaxf(acc[mt][u][0]+b0, 0.f)*w0 + fmaxf(acc[mt][u][1]+b1, 0.f)*w1;
                part[mt*2+1] += fmaxf(acc[mt][u][2]+b0, 0.f)*w0 + fmaxf(acc[mt][u][3]+b1, 0.f)*w1;
            }
        }
        #pragma unroll
        for (int i = 0; i < 8; i++){
            part[i] += __shfl_xor_sync(0xffffffffu, part[i], 1);
            part[i] += __shfl_xor_sync(0xffffffffu, part[i], 2);
        }
        if (qd == 0){
            const int cg = warp >> 1;
            #pragma unroll
            for (int mt = 0; mt < 4; mt++){
                red[(rbase + mt*16 + grp)*4 + cg]     = part[mt*2];
                red[(rbase + mt*16 + grp + 8)*4 + cg] = part[mt*2+1];
            }
        }
        __syncthreads();
        if (tid < 128){
            float s = red[tid*4] + red[tid*4+1] + red[tid*4+2] + red[tid*4+3];
            atomicAdd(&C[m0 + tid], s);
        }
    }
}

// ---------------- tiny SIMT GEMM (M=16 paths, raw f32) ---------------------
__global__ void k_small(const float* __restrict__ A, const float* __restrict__ W,
                        const float* __restrict__ bias, float* __restrict__ C,
                        int M, int N, int K, int act)
{
    int g = blockIdx.x*8 + (threadIdx.x>>5), lane = threadIdx.x & 31;
    int m = g / N, n = g % N;
    if (m >= M) return;
    float s = 0.f;
    for (int k = lane; k < K; k += 32) s = fmaf(A[m*K+k], W[n*K+k], s);
    #pragma unroll
    for (int o = 16; o > 0; o >>= 1) s += __shfl_down_sync(0xffffffffu, s, o);
    if (lane == 0){
        s += bias[n];
        if (act) s = fmaxf(s, 0.f);
        C[m*N+n] = s;
    }
}

// ---------------- scorer3 (defaults path only, 16 rows) --------------------
__global__ void k_scorer3(const float* __restrict__ H2, const float* __restrict__ W3,
                          const float* __restrict__ b3, float* __restrict__ out, int M)
{
    int warp = threadIdx.x >> 5, lane = threadIdx.x & 31;
    int row = blockIdx.x * 8 + warp;
    if (row >= M) return;
    const float* h = H2 + (long long)row * (D_/2);
    float sum = 0.f;
    #pragma unroll
    for (int t = 0; t < 8; t++) sum = fmaf(h[lane + t*32], W3[lane + t*32], sum);
    #pragma unroll
    for (int o = 16; o > 0; o >>= 1) sum += __shfl_down_sync(0xffffffffu, sum, o);
    if (lane == 0) out[row] = tanhf(sum + b3[0]);
}

// ---------------- softmax (fb EMA inlined): 128 thr/row --------------------
__global__ void __launch_bounds__(128)
k_softmax(const float* __restrict__ scores, float* __restrict__ wt,
          float* __restrict__ fbw, const void* __restrict__ maskp,
          const float* __restrict__ fallback)
{
    __shared__ float red[128];
    const int row = blockIdx.x, b = row >> 10, g = threadIdx.x;
    const float* s = scores + (long long)row * LK_ + g*8;
    const int mode = g_maskmode;
    const float bmax = funmap(g_umax), bmin = funmap(g_umin);
    const float fb = 0.99f * fallback[0] + 0.01f * ((bmax + bmin) * 0.5f);

    float4 va = ((const float4*)s)[0];
    float4 vb = ((const float4*)s)[1];
    float x[8] = {va.x,va.y,va.z,va.w, vb.x,vb.y,vb.z,vb.w};
    int mk[8];
    const int mbase = b*LK_ + g*8;
    if (mode == 0){
        uchar4 a = ((const uchar4*)maskp)[(mbase>>2)];
        uchar4 c = ((const uchar4*)maskp)[(mbase>>2)+1];
        mk[0]=a.x!=0; mk[1]=a.y!=0; mk[2]=a.z!=0; mk[3]=a.w!=0;
        mk[4]=c.x!=0; mk[5]=c.y!=0; mk[6]=c.z!=0; mk[7]=c.w!=0;
    } else if (mode == 1){
        int4 a = ((const int4*)maskp)[(mbase>>2)];
        int4 c = ((const int4*)maskp)[(mbase>>2)+1];
        mk[0]=a.x!=0; mk[1]=a.y!=0; mk[2]=a.z!=0; mk[3]=a.w!=0;
        mk[4]=c.x!=0; mk[5]=c.y!=0; mk[6]=c.z!=0; mk[7]=c.w!=0;
    } else {
        float4 a = ((const float4*)maskp)[(mbase>>2)];
        float4 c = ((const float4*)maskp)[(mbase>>2)+1];
        mk[0]=a.x!=0.f; mk[1]=a.y!=0.f; mk[2]=a.z!=0.f; mk[3]=a.w!=0.f;
        mk[4]=c.x!=0.f; mk[5]=c.y!=0.f; mk[6]=c.z!=0.f; mk[7]=c.w!=0.f;
    }
    float lmax = fb;
    #pragma unroll
    for (int c = 0; c < 8; c++) if (!mk[c]) lmax = fmaxf(lmax, x[c]);
    red[g] = lmax; __syncthreads();
    for (int st = 64; st > 0; st >>= 1){
        if (g < st) red[g] = fmaxf(red[g], red[g+st]);
        __syncthreads();
    }
    const float m = red[0];
    __syncthreads();
    float e[8], lsum = 0.f;
    #pragma unroll
    for (int c = 0; c < 8; c++){ e[c] = mk[c] ? 0.f : expf(x[c]-m); lsum += e[c]; }
    red[g] = lsum; __syncthreads();
    for (int st = 64; st > 0; st >>= 1){
        if (g < st) red[g] += red[g+st];
        __syncthreads();
    }
    const float fbe = expf(fb - m);
    const float inv = 1.f / (red[0] + fbe);
    float* w = wt + (long long)row*LK_ + g*8;
    ((float4*)w)[0] = make_float4(tf32r(e[0]*inv), tf32r(e[4]*inv), tf32r(e[1]*inv), tf32r(e[5]*inv));
    ((float4*)w)[1] = make_float4(tf32r(e[2]*inv), tf32r(e[6]*inv), tf32r(e[3]*inv), tf32r(e[7]*inv));
    if (g == 0) fbw[row] = fbe * inv;
}

// ---------------------------------------------------------------------------
#define GA(p, sym) { void* _t; cudaGetSymbolAddress(&_t, sym); p = (float*)_t; }

extern "C" void kernel_launch(void* const* d_in, const int* in_sizes, int n_in,
                              void* d_out, int out_size)
{
    const float* uncond_q = (const float*)d_in[0];
    const float* q  = (const float*)d_in[1];
    const float* k  = (const float*)d_in[2];
    const float* v  = (const float*)d_in[3];
    const void*  mask = d_in[4];
    const float* fallback = (const float*)d_in[5];
    const float* Wv = (const float*)d_in[6];
    const float* bv = (const float*)d_in[7];
    const float* Wf = (const float*)d_in[8];
    const float* bf = (const float*)d_in[9];
    const float* W1 = (const float*)d_in[10];
    const float* b1 = (const float*)d_in[11];
    const float* W2 = (const float*)d_in[12];
    const float* b2 = (const float*)d_in[13];
    const float* W3 = (const float*)d_in[14];
    const float* b3 = (const float*)d_in[15];

    float *qp,*kp,*vpin,*wvp,*w1p,*w2p,*vpt,*scores,*wt,*attn,*h1,*outacc;
    float *fbw,*defv,*dh1,*dh2;
    GA(qp,g_qp); GA(kp,g_kp); GA(vpin,g_vpin);
    GA(wvp,g_wvp); GA(w1p,g_w1p); GA(w2p,g_w2p);
    GA(vpt,g_vpt); GA(scores,g_scores); GA(wt,g_wt);
    GA(attn,g_attn); GA(h1,g_h1); GA(outacc,g_outacc);
    GA(fbw,g_fbw); GA(defv,g_def); GA(dh1,g_dh1); GA(dh2,g_dh2);

    static cudaStream_t s1 = nullptr, s2 = nullptr;
    static cudaEvent_t eF = nullptr, e1 = nullptr, e2 = nullptr, eK = nullptr;
    if (!s1){
        cudaStreamCreateWithFlags(&s1, cudaStreamNonBlocking);
        cudaStreamCreateWithFlags(&s2, cudaStreamNonBlocking);
        cudaEventCreateWithFlags(&eF, cudaEventDisableTiming);
        cudaEventCreateWithFlags(&e1, cudaEventDisableTiming);
        cudaEventCreateWithFlags(&e2, cudaEventDisableTiming);
        cudaEventCreateWithFlags(&eK, cudaEventDisableTiming);
        cudaFuncSetAttribute(k6<0>, cudaFuncAttributeMaxDynamicSharedMemorySize, ENG_SMEM);
        cudaFuncSetAttribute(k6<2>, cudaFuncAttributeMaxDynamicSharedMemorySize, ENG_SMEM);
        cudaFuncSetAttribute(k6<3>, cudaFuncAttributeMaxDynamicSharedMemorySize, ENG_SMEM);
        cudaFuncSetAttribute(k6<5>, cudaFuncAttributeMaxDynamicSharedMemorySize, ENG_SMEM);
        cudaFuncSetAttribute(k6<7>, cudaFuncAttributeMaxDynamicSharedMemorySize, ENG_SMEM);
    }

    const float inv_sqrt_d = 0.04419417382415922f;
    const long long sQ = (long long)LQ_*D_;
    const long long sS = (long long)LQ_*LK_;
    const long long sVT = (long long)D_*LK_;
    float* out = (float*)d_out;
    const int do_out = (out_size >= NROW_ + B_) ? 1 : 0;

    // fork side streams
    cudaEventRecord(eF, 0);
    cudaStreamWaitEvent(s1, eF, 0);
    cudaStreamWaitEvent(s2, eF, 0);

    // ---- s1: v convert + weight converts + vp GEMM ----
    k_cvt1<<<8192, 256, 0, s1>>>((const float4*)v, vpin, NROW_*D_/4);
    k_cvt3<<<dim3(256,3), 256, 0, s1>>>((const float4*)Wv, wvp, (const float4*)W1, w1p,
                                        (const float4*)W2, w2p,
                                        D_*D_/4, D_*D_/4, (D_/2)*D_/4);
    k6<5><<<dim3(4,128,1), 256, ENG_SMEM, s1>>>(vpin, wvp, bv, vpt,
        D_, D_, 0, 0, 0, 1.f, nullptr, nullptr);
    cudaEventRecord(e1, s1);

    // ---- s2: cvt(k) + zero outacc + defaults ----
    k_cvt1<<<8192, 256, 0, s2>>>((const float4*)k, kp, NROW_*D_/4);
    cudaEventRecord(eK, s2);
    k_zero<<<NROW_/256, 256, 0, s2>>>(outacc, NROW_);
    k_small<<<(B_*D_+7)/8, 256, 0, s2>>>(uncond_q, Wf, bf, defv, B_, D_, D_, 0);
    k_small<<<(B_*D_+7)/8, 256, 0, s2>>>(defv, W1, b1, dh1, B_, D_, D_, 1);
    k_small<<<(B_*(D_/2)+7)/8, 256, 0, s2>>>(dh1, W2, b2, dh2, B_, D_/2, D_, 1);
    if (do_out)
        k_scorer3<<<2, 256, 0, s2>>>(dh2, W3, b3, out + NROW_, B_);
    cudaEventRecord(e2, s2);

    // ---- main stream: QK chain ----
    k_init_detect<<<1, 256>>>((const unsigned char*)mask);
    k_cvt1<<<8192, 256>>>((const float4*)q, qp, NROW_*D_/4);
    cudaStreamWaitEvent(0, eK, 0);

    k6<0><<<dim3(8,8,B_), 256, ENG_SMEM>>>(qp, kp, nullptr, scores,
        LK_, D_, sQ, sQ, sS, inv_sqrt_d, nullptr, nullptr);

    k_softmax<<<NROW_, 128>>>(scores, wt, fbw, mask, fallback);

    cudaStreamWaitEvent(0, e1, 0);
    cudaStreamWaitEvent(0, e2, 0);

    k6<2><<<dim3(4,8,B_), 256, ENG_SMEM>>>(wt, vpt, nullptr, attn,
        D_, LK_, sS, sVT, sQ, 1.f, fbw, defv);

    k6<3><<<dim3(4,128,1), 256, ENG_SMEM>>>(attn, w1p, b1, h1,
        D_, D_, 0, 0, 0, 1.f, nullptr, nullptr);

    // W2 GEMM with fused partial scorer dot -> outacc
    k6<7><<<dim3(2,128,1), 256, ENG_SMEM>>>(h1, w2p, b2, outacc,
        D_/2, D_, 0, 0, 0, 1.f, W3, nullptr);

    k_tanh<<<NROW_/256, 256>>>(outacc, b3, out, NROW_);
}